// round 1
// baseline (speedup 1.0000x reference)
#include <cuda_runtime.h>
#include <math.h>

// Problem constants
#define B_   2
#define S_   2048
#define M_   (B_*S_)      // 4096 rows
#define DIM_ 1024
#define DFF_ 4096
#define NH_  16
#define HD_  64
#define EPSV 1e-6f

// ---------------- scratch (device globals; no allocations allowed) ----------
__device__ float g_ln  [M_*DIM_];
__device__ float g_q   [M_*DIM_];
__device__ float g_k   [M_*DIM_];
__device__ float g_v   [M_*DIM_];
__device__ float g_attn[M_*DIM_];
__device__ float g_x1  [M_*DIM_];
__device__ float g_ff  [(size_t)M_*DFF_];

// ---------------- LayerNorm (torch-style: unbiased std, denom = std+eps) ----
__global__ __launch_bounds__(256) void ln_kernel(
    const float* __restrict__ x, const float* __restrict__ alpha,
    const float* __restrict__ beta, float* __restrict__ out)
{
    int row = blockIdx.x;
    const float* xr = x + (size_t)row * DIM_;
    float* orow = out + (size_t)row * DIM_;
    int tid = threadIdx.x;

    float v[4];
    float s = 0.f, s2 = 0.f;
#pragma unroll
    for (int j = 0; j < 4; j++) {
        v[j] = xr[tid + j * 256];
        s += v[j];
        s2 += v[j] * v[j];
    }
#pragma unroll
    for (int o = 16; o > 0; o >>= 1) {
        s  += __shfl_xor_sync(0xffffffffu, s,  o);
        s2 += __shfl_xor_sync(0xffffffffu, s2, o);
    }
    __shared__ float rs[8], rs2[8];
    int wid = tid >> 5, lid = tid & 31;
    if (lid == 0) { rs[wid] = s; rs2[wid] = s2; }
    __syncthreads();
    s = 0.f; s2 = 0.f;
#pragma unroll
    for (int i = 0; i < 8; i++) { s += rs[i]; s2 += rs2[i]; }

    float mu  = s * (1.0f / DIM_);
    float var = (s2 - (float)DIM_ * mu * mu) * (1.0f / (DIM_ - 1));
    float inv = 1.0f / (sqrtf(fmaxf(var, 0.f)) + EPSV);
#pragma unroll
    for (int j = 0; j < 4; j++) {
        int c = tid + j * 256;
        orow[c] = alpha[c] * (v[j] - mu) * inv + beta[c];
    }
}

// ---------------- fp32 GEMM: C[M,N] = A[M,K] @ B[K,N] (+bias, +relu, +resid) -
// 128x128 block tile, 8x8 per thread, K-step 8.
template<int RELU>
__global__ __launch_bounds__(256) void gemm128(
    const float* __restrict__ A, const float* __restrict__ Bm,
    const float* __restrict__ bias, const float* __restrict__ resid,
    float* __restrict__ C, int M, int N, int K)
{
    __shared__ float As[8 * 132];   // padded pitch for conflict-free transposed store
    __shared__ float Bs[8 * 128];

    int tid = threadIdx.x;
    int rowBase = blockIdx.y * 128;
    int colBase = blockIdx.x * 128;
    int ty = tid >> 4, tx = tid & 15;

    float acc[8][8];
#pragma unroll
    for (int i = 0; i < 8; i++)
#pragma unroll
        for (int j = 0; j < 8; j++) acc[i][j] = 0.f;

    int la_r = tid >> 1;           // 0..127
    int la_k = (tid & 1) * 4;      // 0 or 4
    int lb_k = tid >> 5;           // 0..7
    int lb_c = (tid & 31) * 4;     // 0..124

    const float* Aptr = A + (size_t)(rowBase + la_r) * K + la_k;
    const float* Bptr = Bm + (size_t)lb_k * N + colBase + lb_c;

    for (int k0 = 0; k0 < K; k0 += 8) {
        float4 av = *(const float4*)(Aptr + k0);
        float4 bv = *(const float4*)(Bptr + (size_t)k0 * N);
        __syncthreads();
        As[(la_k + 0) * 132 + la_r] = av.x;
        As[(la_k + 1) * 132 + la_r] = av.y;
        As[(la_k + 2) * 132 + la_r] = av.z;
        As[(la_k + 3) * 132 + la_r] = av.w;
        *(float4*)&Bs[lb_k * 128 + lb_c] = bv;
        __syncthreads();
#pragma unroll
        for (int kk = 0; kk < 8; kk++) {
            float4 a0 = *(const float4*)&As[kk * 132 + ty * 8];
            float4 a1 = *(const float4*)&As[kk * 132 + ty * 8 + 4];
            float4 b0 = *(const float4*)&Bs[kk * 128 + tx * 8];
            float4 b1 = *(const float4*)&Bs[kk * 128 + tx * 8 + 4];
            float a_[8] = {a0.x, a0.y, a0.z, a0.w, a1.x, a1.y, a1.z, a1.w};
            float b_[8] = {b0.x, b0.y, b0.z, b0.w, b1.x, b1.y, b1.z, b1.w};
#pragma unroll
            for (int i = 0; i < 8; i++)
#pragma unroll
                for (int j = 0; j < 8; j++)
                    acc[i][j] += a_[i] * b_[j];
        }
    }

    // epilogue
#pragma unroll
    for (int i = 0; i < 8; i++) {
        int r = rowBase + ty * 8 + i;
        size_t rowOff = (size_t)r * N + colBase + tx * 8;
#pragma unroll
        for (int j = 0; j < 8; j++) {
            float vv = acc[i][j];
            if (bias)  vv += bias[colBase + tx * 8 + j];
            if (RELU)  vv = fmaxf(vv, 0.f);
            if (resid) vv += resid[rowOff + j];
            acc[i][j] = vv;
        }
        float4 o0 = make_float4(acc[i][0], acc[i][1], acc[i][2], acc[i][3]);
        float4 o1 = make_float4(acc[i][4], acc[i][5], acc[i][6], acc[i][7]);
        *(float4*)&C[rowOff]     = o0;
        *(float4*)&C[rowOff + 4] = o1;
    }
}

// ---------------- fused flash attention (64x64 tiles, online softmax) -------
// Q,K,V: [M_, DIM_] with column = h*HD + d.  O: same layout (head-concat).
#define AP 68   // smem pitch (floats): 16B-aligned, stride-68 banks avoid conflicts
#define ATTN_SMEM (4 * 64 * AP * 4)

__global__ __launch_bounds__(256) void attn_kernel(
    const float* __restrict__ Q, const float* __restrict__ K,
    const float* __restrict__ V, float* __restrict__ O)
{
    extern __shared__ float sm[];
    float* Qt = sm;              // [d][r]   64 x AP
    float* Kt = Qt + 64 * AP;    // [d][c]
    float* Vs = Kt + 64 * AP;    // [c][d]
    float* Pt = Vs + 64 * AP;    // [c][r]

    int tid = threadIdx.x;
    int qt = blockIdx.x;
    int b  = blockIdx.y >> 4;
    int h  = blockIdx.y & 15;
    int ty = tid >> 4, tx = tid & 15;   // microtile: rows ty*4.., cols tx*4..
    int lr  = tid >> 2;                 // load row 0..63
    int lc0 = (tid & 3) * 16;           // load col chunk

    // load Q tile transposed
    size_t baseQ = ((size_t)(b * S_ + qt * 64 + lr)) * DIM_ + h * HD_ + lc0;
#pragma unroll
    for (int j = 0; j < 16; j++) Qt[(lc0 + j) * AP + lr] = Q[baseQ + j];

    float acc[4][4];
    float m[4], l[4];
#pragma unroll
    for (int i = 0; i < 4; i++) {
        m[i] = -1e30f; l[i] = 0.f;
#pragma unroll
        for (int j = 0; j < 4; j++) acc[i][j] = 0.f;
    }
    const float scale = 0.125f; // 1/sqrt(64)

    for (int kt = 0; kt < S_ / 64; kt++) {
        size_t baseK = ((size_t)(b * S_ + kt * 64 + lr)) * DIM_ + h * HD_ + lc0;
        __syncthreads();   // protect prior-iter smem reads (also Qt visibility, iter 0)
#pragma unroll
        for (int j = 0; j < 16; j++) Kt[(lc0 + j) * AP + lr] = K[baseK + j];
#pragma unroll
        for (int j = 0; j < 4; j++)
            *(float4*)&Vs[lr * AP + lc0 + j * 4] = *(const float4*)&V[baseK + j * 4];
        __syncthreads();

        // S = (Q K^T) * scale  (4x4 microtile per thread)
        float s[4][4];
#pragma unroll
        for (int i = 0; i < 4; i++)
#pragma unroll
            for (int j = 0; j < 4; j++) s[i][j] = 0.f;

#pragma unroll 4
        for (int d = 0; d < 64; d++) {
            float4 a = *(const float4*)&Qt[d * AP + ty * 4];
            float4 bk = *(const float4*)&Kt[d * AP + tx * 4];
            float a_[4] = {a.x, a.y, a.z, a.w};
            float b_[4] = {bk.x, bk.y, bk.z, bk.w};
#pragma unroll
            for (int i = 0; i < 4; i++)
#pragma unroll
                for (int j = 0; j < 4; j++)
                    s[i][j] += a_[i] * b_[j];
        }

        // online softmax (row stats across the 16-lane half-warp groups)
#pragma unroll
        for (int i = 0; i < 4; i++) {
#pragma unroll
            for (int j = 0; j < 4; j++) s[i][j] *= scale;
            float mx = fmaxf(fmaxf(s[i][0], s[i][1]), fmaxf(s[i][2], s[i][3]));
#pragma unroll
            for (int o = 1; o < 16; o <<= 1)
                mx = fmaxf(mx, __shfl_xor_sync(0xffffffffu, mx, o));
            float mn = fmaxf(m[i], mx);
            float corr = __expf(m[i] - mn);
            float rsum = 0.f;
#pragma unroll
            for (int j = 0; j < 4; j++) {
                s[i][j] = __expf(s[i][j] - mn);
                rsum += s[i][j];
            }
#pragma unroll
            for (int o = 1; o < 16; o <<= 1)
                rsum += __shfl_xor_sync(0xffffffffu, rsum, o);
            l[i] = l[i] * corr + rsum;
            m[i] = mn;
#pragma unroll
            for (int j = 0; j < 4; j++) acc[i][j] *= corr;
            // store P transposed for the PV microtile GEMM
#pragma unroll
            for (int j = 0; j < 4; j++)
                Pt[(tx * 4 + j) * AP + ty * 4 + i] = s[i][j];
        }
        __syncthreads();

        // O += P @ V
#pragma unroll 4
        for (int c = 0; c < 64; c++) {
            float4 p  = *(const float4*)&Pt[c * AP + ty * 4];
            float4 vv = *(const float4*)&Vs[c * AP + tx * 4];
            float p_[4] = {p.x, p.y, p.z, p.w};
            float v_[4] = {vv.x, vv.y, vv.z, vv.w};
#pragma unroll
            for (int i = 0; i < 4; i++)
#pragma unroll
                for (int j = 0; j < 4; j++)
                    acc[i][j] += p_[i] * v_[j];
        }
    }

    // write normalized output (head-concat layout)
#pragma unroll
    for (int i = 0; i < 4; i++) {
        float invl = 1.0f / l[i];
        int r = qt * 64 + ty * 4 + i;
        size_t off = ((size_t)(b * S_ + r)) * DIM_ + h * HD_ + tx * 4;
        float4 o4 = make_float4(acc[i][0] * invl, acc[i][1] * invl,
                                acc[i][2] * invl, acc[i][3] * invl);
        *(float4*)&O[off] = o4;
    }
}

// ---------------- launcher ---------------------------------------------------
extern "C" void kernel_launch(void* const* d_in, const int* in_sizes, int n_in,
                              void* d_out, int out_size)
{
    const float* x      = (const float*)d_in[0];
    // d_in[1]: mask (bool) — no-op in reference, ignored
    const float* wq     = (const float*)d_in[2];
    const float* wk     = (const float*)d_in[3];
    const float* wv     = (const float*)d_in[4];
    const float* wo     = (const float*)d_in[5];
    const float* w_up   = (const float*)d_in[6];
    const float* b_up   = (const float*)d_in[7];
    const float* w_down = (const float*)d_in[8];
    const float* b_down = (const float*)d_in[9];
    const float* ln1_a  = (const float*)d_in[10];
    const float* ln1_b  = (const float*)d_in[11];
    const float* ln2_a  = (const float*)d_in[12];
    const float* ln2_b  = (const float*)d_in[13];
    float* out = (float*)d_out;

    float *p_ln, *p_q, *p_k, *p_v, *p_attn, *p_x1, *p_ff;
    cudaGetSymbolAddress((void**)&p_ln,   g_ln);
    cudaGetSymbolAddress((void**)&p_q,    g_q);
    cudaGetSymbolAddress((void**)&p_k,    g_k);
    cudaGetSymbolAddress((void**)&p_v,    g_v);
    cudaGetSymbolAddress((void**)&p_attn, g_attn);
    cudaGetSymbolAddress((void**)&p_x1,   g_x1);
    cudaGetSymbolAddress((void**)&p_ff,   g_ff);

    dim3 blk(256);
    dim3 gD(DIM_ / 128, M_ / 128);   // N=1024 GEMMs
    dim3 gF(DFF_ / 128, M_ / 128);   // N=4096 GEMM

    // h = LN1(x)
    ln_kernel<<<M_, blk>>>(x, ln1_a, ln1_b, p_ln);
    // Q,K,V projections
    gemm128<0><<<gD, blk>>>(p_ln, wq, nullptr, nullptr, p_q, M_, DIM_, DIM_);
    gemm128<0><<<gD, blk>>>(p_ln, wk, nullptr, nullptr, p_k, M_, DIM_, DIM_);
    gemm128<0><<<gD, blk>>>(p_ln, wv, nullptr, nullptr, p_v, M_, DIM_, DIM_);
    // fused attention
    cudaFuncSetAttribute(attn_kernel, cudaFuncAttributeMaxDynamicSharedMemorySize, ATTN_SMEM);
    attn_kernel<<<dim3(S_ / 64, B_ * NH_), blk, ATTN_SMEM>>>(p_q, p_k, p_v, p_attn);
    // x1 = x + attn @ wo
    gemm128<0><<<gD, blk>>>(p_attn, wo, nullptr, x, p_x1, M_, DIM_, DIM_);
    // h = LN2(x1)
    ln_kernel<<<M_, blk>>>(p_x1, ln2_a, ln2_b, p_ln);
    // ff = relu(h @ w_up + b_up)
    gemm128<1><<<gF, blk>>>(p_ln, w_up, b_up, nullptr, p_ff, M_, DFF_, DIM_);
    // out = x1 + ff @ w_down + b_down
    gemm128<0><<<gD, blk>>>(p_ff, w_down, b_down, p_x1, out, M_, DIM_, DFF_);
}

// round 4
// speedup vs baseline: 1.7070x; 1.7070x over previous
#include <cuda_runtime.h>
#include <cuda_bf16.h>
#include <cstdint>
#include <math.h>

// Problem constants
#define B_   2
#define S_   2048
#define M_   (B_*S_)      // 4096 rows
#define DIM_ 1024
#define DFF_ 4096
#define NH_  16
#define HD_  64
#define EPSV 1e-6f

typedef __nv_bfloat16 bf16;

// ---------------- scratch (device globals; no allocations allowed) ----------
__device__ __align__(16) bf16  g_lnH [M_*DIM_];
__device__ __align__(16) bf16  g_lnL [M_*DIM_];
__device__ __align__(16) float g_q   [M_*DIM_];
__device__ __align__(16) float g_k   [M_*DIM_];
__device__ __align__(16) float g_v   [M_*DIM_];
__device__ __align__(16) bf16  g_atH [M_*DIM_];
__device__ __align__(16) bf16  g_atL [M_*DIM_];
__device__ __align__(16) float g_x1  [M_*DIM_];
__device__ __align__(16) bf16  g_ffH [(size_t)M_*DFF_];
__device__ __align__(16) bf16  g_ffL [(size_t)M_*DFF_];
// transposed weights, hi/lo bf16 planes, layout [N][K]
__device__ __align__(16) bf16  g_wqH [DIM_*DIM_], g_wqL [DIM_*DIM_];
__device__ __align__(16) bf16  g_wkH [DIM_*DIM_], g_wkL [DIM_*DIM_];
__device__ __align__(16) bf16  g_wvH [DIM_*DIM_], g_wvL [DIM_*DIM_];
__device__ __align__(16) bf16  g_woH [DIM_*DIM_], g_woL [DIM_*DIM_];
__device__ __align__(16) bf16  g_upH [(size_t)DFF_*DIM_], g_upL [(size_t)DFF_*DIM_];
__device__ __align__(16) bf16  g_dnH [(size_t)DIM_*DFF_], g_dnL [(size_t)DIM_*DFF_];

// ---------------- PTX helpers ------------------------------------------------
__device__ __forceinline__ uint32_t smem_u32(const void* p) {
    uint32_t a;
    asm("{ .reg .u64 t; cvta.to.shared.u64 t, %1; cvt.u32.u64 %0, t; }" : "=r"(a) : "l"(p));
    return a;
}
__device__ __forceinline__ void cp_async16(uint32_t saddr, const void* gaddr) {
    asm volatile("cp.async.cg.shared.global [%0], [%1], 16;" :: "r"(saddr), "l"(gaddr) : "memory");
}
__device__ __forceinline__ void cp_commit() {
    asm volatile("cp.async.commit_group;" ::: "memory");
}
template<int N>
__device__ __forceinline__ void cp_wait() {
    asm volatile("cp.async.wait_group %0;" :: "n"(N) : "memory");
}
__device__ __forceinline__ void ldm_x4(uint32_t& r0, uint32_t& r1, uint32_t& r2, uint32_t& r3,
                                       uint32_t addr) {
    asm volatile("ldmatrix.sync.aligned.m8n8.x4.shared.b16 {%0,%1,%2,%3}, [%4];"
                 : "=r"(r0), "=r"(r1), "=r"(r2), "=r"(r3) : "r"(addr));
}
__device__ __forceinline__ void ldm_x2(uint32_t& r0, uint32_t& r1, uint32_t addr) {
    asm volatile("ldmatrix.sync.aligned.m8n8.x2.shared.b16 {%0,%1}, [%2];"
                 : "=r"(r0), "=r"(r1) : "r"(addr));
}
__device__ __forceinline__ void mma_bf16(float* c, const uint32_t* a, const uint32_t* b) {
    asm volatile("mma.sync.aligned.m16n8k16.row.col.f32.bf16.bf16.f32 "
                 "{%0,%1,%2,%3}, {%4,%5,%6,%7}, {%8,%9}, {%0,%1,%2,%3};"
                 : "+f"(c[0]), "+f"(c[1]), "+f"(c[2]), "+f"(c[3])
                 : "r"(a[0]), "r"(a[1]), "r"(a[2]), "r"(a[3]), "r"(b[0]), "r"(b[1]));
}

// ---------------- weight transpose + hi/lo bf16 conversion -------------------
// W[K][N] fp32 -> TH/TL[N][K] bf16
__global__ __launch_bounds__(256) void conv_w(const float* __restrict__ W,
    bf16* __restrict__ TH, bf16* __restrict__ TL, int K, int N)
{
    __shared__ float t[32][33];
    int nt = blockIdx.x * 32, kt = blockIdx.y * 32;
    int tx = threadIdx.x, ty = threadIdx.y;
#pragma unroll
    for (int j = 0; j < 4; j++)
        t[ty + j * 8][tx] = W[(size_t)(kt + ty + j * 8) * N + nt + tx];
    __syncthreads();
#pragma unroll
    for (int j = 0; j < 4; j++) {
        int n = nt + ty + j * 8;
        float v = t[tx][ty + j * 8];
        bf16 h = __float2bfloat16(v);
        TH[(size_t)n * K + kt + tx] = h;
        TL[(size_t)n * K + kt + tx] = __float2bfloat16(v - __bfloat162float(h));
    }
}

// ---------------- LayerNorm -> hi/lo bf16 planes -----------------------------
__global__ __launch_bounds__(256) void ln_kernel(
    const float* __restrict__ x, const float* __restrict__ alpha,
    const float* __restrict__ beta, bf16* __restrict__ outH, bf16* __restrict__ outL)
{
    int row = blockIdx.x;
    const float* xr = x + (size_t)row * DIM_;
    int tid = threadIdx.x;

    float v[4];
    float s = 0.f, s2 = 0.f;
#pragma unroll
    for (int j = 0; j < 4; j++) {
        v[j] = xr[tid + j * 256];
        s += v[j]; s2 += v[j] * v[j];
    }
#pragma unroll
    for (int o = 16; o > 0; o >>= 1) {
        s  += __shfl_xor_sync(0xffffffffu, s,  o);
        s2 += __shfl_xor_sync(0xffffffffu, s2, o);
    }
    __shared__ float rs[8], rs2[8];
    int wid = tid >> 5, lid = tid & 31;
    if (lid == 0) { rs[wid] = s; rs2[wid] = s2; }
    __syncthreads();
    s = 0.f; s2 = 0.f;
#pragma unroll
    for (int i = 0; i < 8; i++) { s += rs[i]; s2 += rs2[i]; }

    float mu  = s * (1.0f / DIM_);
    float var = (s2 - (float)DIM_ * mu * mu) * (1.0f / (DIM_ - 1));
    float inv = 1.0f / (sqrtf(fmaxf(var, 0.f)) + EPSV);
#pragma unroll
    for (int j = 0; j < 4; j++) {
        int c = tid + j * 256;
        float y = alpha[c] * (v[j] - mu) * inv + beta[c];
        bf16 h = __float2bfloat16(y);
        size_t o = (size_t)row * DIM_ + c;
        outH[o] = h;
        outL[o] = __float2bfloat16(y - __bfloat162float(h));
    }
}

// ---------------- HMMA GEMM: C[M,N] = A[M,K] @ Wt[N,K]^T ---------------------
// A,B as hi/lo bf16 planes; D = Ah*Bh + Ah*Bl + Al*Bh (fp32 accum in regs).
// CTA tile 128x128, 8 warps of 64x32, K-chunk 64, cp.async double buffer.
// SMEM tile: 128 rows x 64 bf16 (128B data), row pitch 144B (bank-stagger).
#define PITCH 144
#define PLANE_BYTES (128 * PITCH)              // 18432
#define STAGE_BYTES (4 * PLANE_BYTES)          // AH, AL, BH, BL = 73728
#define GEMM_SMEM   (2 * STAGE_BYTES + 256)

__global__ __launch_bounds__(256, 1)
void gemm_hmma(const bf16* __restrict__ AH, const bf16* __restrict__ AL,
               const bf16* __restrict__ BH, const bf16* __restrict__ BL,
               const float* __restrict__ bias, const float* __restrict__ resid,
               float* __restrict__ Cf, bf16* __restrict__ CH, bf16* __restrict__ CL,
               int M, int N, int K, int relu)
{
    extern __shared__ char dsm[];
    char* sb = (char*)(((uintptr_t)dsm + 127) & ~(uintptr_t)127);
    uint32_t sb32 = smem_u32(sb);

    int tid = threadIdx.x, wid = tid >> 5, lane = tid & 31;
    int rowBase = blockIdx.y * 128, colBase = blockIdx.x * 128;
    int wm = wid & 1, wn = wid >> 1;           // warp tile: rows wm*64, cols wn*32

    const bf16* planes[4] = {AH, AL, BH, BL};

    float acc[4][4][4];
#pragma unroll
    for (int i = 0; i < 4; i++)
#pragma unroll
        for (int j = 0; j < 4; j++)
#pragma unroll
            for (int q = 0; q < 4; q++) acc[i][j][q] = 0.f;

    // ldmatrix base addresses (per-lane, plane-relative)
    uint32_t aRow = (uint32_t)(wm * 64 + (lane & 15));
    uint32_t aCol = (uint32_t)((lane >> 4) * 16);
    uint32_t bRow = (uint32_t)(wn * 32 + (lane & 7));
    uint32_t bCol = (uint32_t)(((lane >> 3) & 1) * 16);

    int NC = K >> 6;   // 64-wide K chunks

    // ---- stage loader: 4 planes x 128 rows x 8 16B-chunks = 4096 transfers
    auto load_stage = [&](int ch, int s) {
        int k0 = ch << 6;
        uint32_t stage = sb32 + s * STAGE_BYTES;
#pragma unroll
        for (int it = 0; it < 16; it++) {
            int idx = it * 256 + tid;
            int pl = idx >> 10;           // 0..3
            int rem = idx & 1023;
            int r = rem >> 3;             // 0..127
            int c = rem & 7;              // 16B chunk (8 per 128B row)
            int rb = (pl < 2) ? rowBase : colBase;
            const bf16* src = planes[pl] + (size_t)(rb + r) * K + k0 + c * 8;
            uint32_t dst = stage + pl * PLANE_BYTES + r * PITCH + c * 16;
            cp_async16(dst, src);
        }
        cp_commit();
    };

    load_stage(0, 0);

    for (int ch = 0; ch < NC; ch++) {
        int s = ch & 1;
        if (ch + 1 < NC) { load_stage(ch + 1, s ^ 1); cp_wait<1>(); }
        else             { cp_wait<0>(); }
        __syncthreads();

        uint32_t stage = sb32 + s * STAGE_BYTES;
        uint32_t aBaseH = stage + 0 * PLANE_BYTES + aRow * PITCH + aCol;
        uint32_t aBaseL = stage + 1 * PLANE_BYTES + aRow * PITCH + aCol;
        uint32_t bBaseH = stage + 2 * PLANE_BYTES + bRow * PITCH + bCol;
        uint32_t bBaseL = stage + 3 * PLANE_BYTES + bRow * PITCH + bCol;

#pragma unroll
        for (int ks = 0; ks < 4; ks++) {
            uint32_t kOff = ks * 32;
            uint32_t aF[2][4][4], bF[2][4][2];
#pragma unroll
            for (int mt = 0; mt < 4; mt++) {
                ldm_x4(aF[0][mt][0], aF[0][mt][1], aF[0][mt][2], aF[0][mt][3],
                       aBaseH + mt * (16 * PITCH) + kOff);
                ldm_x4(aF[1][mt][0], aF[1][mt][1], aF[1][mt][2], aF[1][mt][3],
                       aBaseL + mt * (16 * PITCH) + kOff);
            }
#pragma unroll
            for (int nt = 0; nt < 4; nt++) {
                ldm_x2(bF[0][nt][0], bF[0][nt][1], bBaseH + nt * (8 * PITCH) + kOff);
                ldm_x2(bF[1][nt][0], bF[1][nt][1], bBaseL + nt * (8 * PITCH) + kOff);
            }
            // pass 0: Ah*Bh ; pass 1: Ah*Bl ; pass 2: Al*Bh
#pragma unroll
            for (int mt = 0; mt < 4; mt++)
#pragma unroll
                for (int nt = 0; nt < 4; nt++) {
                    mma_bf16(acc[mt][nt], aF[0][mt], bF[0][nt]);
                    mma_bf16(acc[mt][nt], aF[0][mt], bF[1][nt]);
                    mma_bf16(acc[mt][nt], aF[1][mt], bF[0][nt]);
                }
        }
        __syncthreads();
    }

    // ---- epilogue: per-thread fragment (rows t/4 and t/4+8, cols 2*(t%4)) ----
    int tr = lane >> 2;         // 0..7
    int tc = (lane & 3) * 2;    // 0,2,4,6
#pragma unroll
    for (int mt = 0; mt < 4; mt++) {
#pragma unroll
        for (int half = 0; half < 2; half++) {
            int r = rowBase + wm * 64 + mt * 16 + tr + half * 8;
#pragma unroll
            for (int nt = 0; nt < 4; nt++) {
                int cg = colBase + wn * 32 + nt * 8 + tc;
                size_t off = (size_t)r * N + cg;
                float v0 = acc[mt][nt][half * 2 + 0];
                float v1 = acc[mt][nt][half * 2 + 1];
                if (bias)  { v0 += bias[cg]; v1 += bias[cg + 1]; }
                if (relu)  { v0 = fmaxf(v0, 0.f); v1 = fmaxf(v1, 0.f); }
                if (resid) { v0 += resid[off]; v1 += resid[off + 1]; }
                if (Cf) {
                    float2 o2 = make_float2(v0, v1);
                    *(float2*)&Cf[off] = o2;
                }
                if (CH) {
                    bf16 h0 = __float2bfloat16(v0);
                    bf16 h1 = __float2bfloat16(v1);
                    __nv_bfloat162 hp; hp.x = h0; hp.y = h1;
                    *(__nv_bfloat162*)&CH[off] = hp;
                    __nv_bfloat162 lp;
                    lp.x = __float2bfloat16(v0 - __bfloat162float(h0));
                    lp.y = __float2bfloat16(v1 - __bfloat162float(h1));
                    *(__nv_bfloat162*)&CL[off] = lp;
                }
            }
        }
    }
}

// ---------------- fused flash attention (fp32 FFMA, 64x64 tiles) -------------
#define AP 68
#define ATTN_SMEM (4 * 64 * AP * 4)

__global__ __launch_bounds__(256) void attn_kernel(
    const float* __restrict__ Q, const float* __restrict__ K,
    const float* __restrict__ V, bf16* __restrict__ OH, bf16* __restrict__ OL)
{
    extern __shared__ float sm[];
    float* Qt = sm;
    float* Kt = Qt + 64 * AP;
    float* Vs = Kt + 64 * AP;
    float* Pt = Vs + 64 * AP;

    int tid = threadIdx.x;
    int qt = blockIdx.x;
    int b  = blockIdx.y >> 4;
    int h  = blockIdx.y & 15;
    int ty = tid >> 4, tx = tid & 15;
    int lr  = tid >> 2;
    int lc0 = (tid & 3) * 16;

    size_t baseQ = ((size_t)(b * S_ + qt * 64 + lr)) * DIM_ + h * HD_ + lc0;
#pragma unroll
    for (int j = 0; j < 16; j++) Qt[(lc0 + j) * AP + lr] = Q[baseQ + j];

    float acc[4][4];
    float m[4], l[4];
#pragma unroll
    for (int i = 0; i < 4; i++) {
        m[i] = -1e30f; l[i] = 0.f;
#pragma unroll
        for (int j = 0; j < 4; j++) acc[i][j] = 0.f;
    }
    const float scale = 0.125f;

    for (int kt = 0; kt < S_ / 64; kt++) {
        size_t baseK = ((size_t)(b * S_ + kt * 64 + lr)) * DIM_ + h * HD_ + lc0;
        __syncthreads();
#pragma unroll
        for (int j = 0; j < 16; j++) Kt[(lc0 + j) * AP + lr] = K[baseK + j];
#pragma unroll
        for (int j = 0; j < 4; j++)
            *(float4*)&Vs[lr * AP + lc0 + j * 4] = *(const float4*)&V[baseK + j * 4];
        __syncthreads();

        float s[4][4];
#pragma unroll
        for (int i = 0; i < 4; i++)
#pragma unroll
            for (int j = 0; j < 4; j++) s[i][j] = 0.f;

#pragma unroll 4
        for (int d = 0; d < 64; d++) {
            float4 a = *(const float4*)&Qt[d * AP + ty * 4];
            float4 bk = *(const float4*)&Kt[d * AP + tx * 4];
            float a_[4] = {a.x, a.y, a.z, a.w};
            float b_[4] = {bk.x, bk.y, bk.z, bk.w};
#pragma unroll
            for (int i = 0; i < 4; i++)
#pragma unroll
                for (int j = 0; j < 4; j++)
                    s[i][j] += a_[i] * b_[j];
        }

#pragma unroll
        for (int i = 0; i < 4; i++) {
#pragma unroll
            for (int j = 0; j < 4; j++) s[i][j] *= scale;
            float mx = fmaxf(fmaxf(s[i][0], s[i][1]), fmaxf(s[i][2], s[i][3]));
#pragma unroll
            for (int o = 1; o < 16; o <<= 1)
                mx = fmaxf(mx, __shfl_xor_sync(0xffffffffu, mx, o));
            float mn = fmaxf(m[i], mx);
            float corr = __expf(m[i] - mn);
            float rsum = 0.f;
#pragma unroll
            for (int j = 0; j < 4; j++) {
                s[i][j] = __expf(s[i][j] - mn);
                rsum += s[i][j];
            }
#pragma unroll
            for (int o = 1; o < 16; o <<= 1)
                rsum += __shfl_xor_sync(0xffffffffu, rsum, o);
            l[i] = l[i] * corr + rsum;
            m[i] = mn;
#pragma unroll
            for (int j = 0; j < 4; j++) acc[i][j] *= corr;
#pragma unroll
            for (int j = 0; j < 4; j++)
                Pt[(tx * 4 + j) * AP + ty * 4 + i] = s[i][j];
        }
        __syncthreads();

#pragma unroll 4
        for (int c = 0; c < 64; c++) {
            float4 p  = *(const float4*)&Pt[c * AP + ty * 4];
            float4 vvv = *(const float4*)&Vs[c * AP + tx * 4];
            float p_[4] = {p.x, p.y, p.z, p.w};
            float v_[4] = {vvv.x, vvv.y, vvv.z, vvv.w};
#pragma unroll
            for (int i = 0; i < 4; i++)
#pragma unroll
                for (int j = 0; j < 4; j++)
                    acc[i][j] += p_[i] * v_[j];
        }
    }

#pragma unroll
    for (int i = 0; i < 4; i++) {
        float invl = 1.0f / l[i];
        int r = qt * 64 + ty * 4 + i;
        size_t off = ((size_t)(b * S_ + r)) * DIM_ + h * HD_ + tx * 4;
#pragma unroll
        for (int j = 0; j < 4; j++) {
            float v = acc[i][j] * invl;
            bf16 hh = __float2bfloat16(v);
            OH[off + j] = hh;
            OL[off + j] = __float2bfloat16(v - __bfloat162float(hh));
        }
    }
}

// ---------------- launcher ---------------------------------------------------
extern "C" void kernel_launch(void* const* d_in, const int* in_sizes, int n_in,
                              void* d_out, int out_size)
{
    const float* x      = (const float*)d_in[0];
    const float* wq     = (const float*)d_in[2];
    const float* wk     = (const float*)d_in[3];
    const float* wv     = (const float*)d_in[4];
    const float* wo     = (const float*)d_in[5];
    const float* w_up   = (const float*)d_in[6];
    const float* b_up   = (const float*)d_in[7];
    const float* w_down = (const float*)d_in[8];
    const float* b_down = (const float*)d_in[9];
    const float* ln1_a  = (const float*)d_in[10];
    const float* ln1_b  = (const float*)d_in[11];
    const float* ln2_a  = (const float*)d_in[12];
    const float* ln2_b  = (const float*)d_in[13];
    float* out = (float*)d_out;

    bf16 *lnH, *lnL, *atH, *atL, *ffH, *ffL;
    bf16 *wqH, *wqL, *wkH, *wkL, *wvH, *wvL, *woH, *woL, *upH, *upL, *dnH, *dnL;
    float *pq, *pk, *pv, *px1;
    cudaGetSymbolAddress((void**)&lnH, g_lnH);  cudaGetSymbolAddress((void**)&lnL, g_lnL);
    cudaGetSymbolAddress((void**)&atH, g_atH);  cudaGetSymbolAddress((void**)&atL, g_atL);
    cudaGetSymbolAddress((void**)&ffH, g_ffH);  cudaGetSymbolAddress((void**)&ffL, g_ffL);
    cudaGetSymbolAddress((void**)&wqH, g_wqH);  cudaGetSymbolAddress((void**)&wqL, g_wqL);
    cudaGetSymbolAddress((void**)&wkH, g_wkH);  cudaGetSymbolAddress((void**)&wkL, g_wkL);
    cudaGetSymbolAddress((void**)&wvH, g_wvH);  cudaGetSymbolAddress((void**)&wvL, g_wvL);
    cudaGetSymbolAddress((void**)&woH, g_woH);  cudaGetSymbolAddress((void**)&woL, g_woL);
    cudaGetSymbolAddress((void**)&upH, g_upH);  cudaGetSymbolAddress((void**)&upL, g_upL);
    cudaGetSymbolAddress((void**)&dnH, g_dnH);  cudaGetSymbolAddress((void**)&dnL, g_dnL);
    cudaGetSymbolAddress((void**)&pq, g_q);     cudaGetSymbolAddress((void**)&pk, g_k);
    cudaGetSymbolAddress((void**)&pv, g_v);     cudaGetSymbolAddress((void**)&px1, g_x1);

    cudaFuncSetAttribute(gemm_hmma, cudaFuncAttributeMaxDynamicSharedMemorySize, GEMM_SMEM);
    cudaFuncSetAttribute(attn_kernel, cudaFuncAttributeMaxDynamicSharedMemorySize, ATTN_SMEM);

    dim3 cblk(32, 8);
    // weight transpose + hi/lo conversion:  W[K][N] -> Wt[N][K]
    conv_w<<<dim3(DIM_/32, DIM_/32), cblk>>>(wq, wqH, wqL, DIM_, DIM_);
    conv_w<<<dim3(DIM_/32, DIM_/32), cblk>>>(wk, wkH, wkL, DIM_, DIM_);
    conv_w<<<dim3(DIM_/32, DIM_/32), cblk>>>(wv, wvH, wvL, DIM_, DIM_);
    conv_w<<<dim3(DIM_/32, DIM_/32), cblk>>>(wo, woH, woL, DIM_, DIM_);
    conv_w<<<dim3(DFF_/32, DIM_/32), cblk>>>(w_up, upH, upL, DIM_, DFF_);
    conv_w<<<dim3(DIM_/32, DFF_/32), cblk>>>(w_down, dnH, dnL, DFF_, DIM_);

    dim3 blk(256);
    dim3 gD(DIM_/128, M_/128);
    dim3 gF(DFF_/128, M_/128);

    // h = LN1(x) -> hi/lo planes
    ln_kernel<<<M_, blk>>>(x, ln1_a, ln1_b, lnH, lnL);
    // Q,K,V projections (HMMA tensor cores)
    gemm_hmma<<<gD, blk, GEMM_SMEM>>>(lnH, lnL, wqH, wqL, nullptr, nullptr,
                                      pq, nullptr, nullptr, M_, DIM_, DIM_, 0);
    gemm_hmma<<<gD, blk, GEMM_SMEM>>>(lnH, lnL, wkH, wkL, nullptr, nullptr,
                                      pk, nullptr, nullptr, M_, DIM_, DIM_, 0);
    gemm_hmma<<<gD, blk, GEMM_SMEM>>>(lnH, lnL, wvH, wvL, nullptr, nullptr,
                                      pv, nullptr, nullptr, M_, DIM_, DIM_, 0);
    // fused attention -> hi/lo planes
    attn_kernel<<<dim3(S_/64, B_*NH_), blk, ATTN_SMEM>>>(pq, pk, pv, atH, atL);
    // x1 = x + attn @ wo
    gemm_hmma<<<gD, blk, GEMM_SMEM>>>(atH, atL, woH, woL, nullptr, x,
                                      px1, nullptr, nullptr, M_, DIM_, DIM_, 0);
    // h = LN2(x1)
    ln_kernel<<<M_, blk>>>(px1, ln2_a, ln2_b, lnH, lnL);
    // ff = relu(h @ w_up + b_up) -> hi/lo planes
    gemm_hmma<<<gF, blk, GEMM_SMEM>>>(lnH, lnL, upH, upL, b_up, nullptr,
                                      nullptr, ffH, ffL, M_, DFF_, DIM_, 1);
    // out = x1 + ff @ w_down + b_down
    gemm_hmma<<<gD, blk, GEMM_SMEM>>>(ffH, ffL, dnH, dnL, b_down, px1,
                                      out, nullptr, nullptr, M_, DIM_, DFF_, 0);
}

// round 5
// speedup vs baseline: 2.8562x; 1.6733x over previous
#include <cuda_runtime.h>
#include <cuda_bf16.h>
#include <cstdint>
#include <math.h>

// Problem constants
#define B_   2
#define S_   2048
#define M_   (B_*S_)      // 4096 rows
#define DIM_ 1024
#define DFF_ 4096
#define NH_  16
#define HD_  64
#define EPSV 1e-6f

typedef __nv_bfloat16 bf16;

// ---------------- scratch (device globals; no allocations allowed) ----------
__device__ __align__(16) bf16  g_lnH [M_*DIM_];
__device__ __align__(16) bf16  g_lnL [M_*DIM_];
__device__ __align__(16) bf16  g_qkvH[(size_t)M_*3*DIM_];
__device__ __align__(16) bf16  g_qkvL[(size_t)M_*3*DIM_];
__device__ __align__(16) bf16  g_atH [M_*DIM_];
__device__ __align__(16) bf16  g_atL [M_*DIM_];
__device__ __align__(16) float g_x1  [M_*DIM_];
__device__ __align__(16) bf16  g_ffH [(size_t)M_*DFF_];
__device__ __align__(16) bf16  g_ffL [(size_t)M_*DFF_];
// transposed weights, hi/lo bf16 planes, layout [N][K]
__device__ __align__(16) bf16  g_wqkvH[(size_t)3*DIM_*DIM_], g_wqkvL[(size_t)3*DIM_*DIM_];
__device__ __align__(16) bf16  g_woH [DIM_*DIM_], g_woL [DIM_*DIM_];
__device__ __align__(16) bf16  g_upH [(size_t)DFF_*DIM_], g_upL [(size_t)DFF_*DIM_];
__device__ __align__(16) bf16  g_dnH [(size_t)DIM_*DFF_], g_dnL [(size_t)DIM_*DFF_];

// ---------------- PTX helpers ------------------------------------------------
__device__ __forceinline__ uint32_t smem_u32(const void* p) {
    uint32_t a;
    asm("{ .reg .u64 t; cvta.to.shared.u64 t, %1; cvt.u32.u64 %0, t; }" : "=r"(a) : "l"(p));
    return a;
}
__device__ __forceinline__ void cp_async16(uint32_t saddr, const void* gaddr) {
    asm volatile("cp.async.cg.shared.global [%0], [%1], 16;" :: "r"(saddr), "l"(gaddr) : "memory");
}
__device__ __forceinline__ void cp_commit() {
    asm volatile("cp.async.commit_group;" ::: "memory");
}
template<int N>
__device__ __forceinline__ void cp_wait() {
    asm volatile("cp.async.wait_group %0;" :: "n"(N) : "memory");
}
__device__ __forceinline__ void ldm_x4(uint32_t& r0, uint32_t& r1, uint32_t& r2, uint32_t& r3,
                                       uint32_t addr) {
    asm volatile("ldmatrix.sync.aligned.m8n8.x4.shared.b16 {%0,%1,%2,%3}, [%4];"
                 : "=r"(r0), "=r"(r1), "=r"(r2), "=r"(r3) : "r"(addr));
}
__device__ __forceinline__ void ldm_x4t(uint32_t& r0, uint32_t& r1, uint32_t& r2, uint32_t& r3,
                                        uint32_t addr) {
    asm volatile("ldmatrix.sync.aligned.m8n8.x4.trans.shared.b16 {%0,%1,%2,%3}, [%4];"
                 : "=r"(r0), "=r"(r1), "=r"(r2), "=r"(r3) : "r"(addr));
}
__device__ __forceinline__ void ldm_x2(uint32_t& r0, uint32_t& r1, uint32_t addr) {
    asm volatile("ldmatrix.sync.aligned.m8n8.x2.shared.b16 {%0,%1}, [%2];"
                 : "=r"(r0), "=r"(r1) : "r"(addr));
}
__device__ __forceinline__ void mma_bf16(float* c, const uint32_t* a, const uint32_t* b) {
    asm volatile("mma.sync.aligned.m16n8k16.row.col.f32.bf16.bf16.f32 "
                 "{%0,%1,%2,%3}, {%4,%5,%6,%7}, {%8,%9}, {%0,%1,%2,%3};"
                 : "+f"(c[0]), "+f"(c[1]), "+f"(c[2]), "+f"(c[3])
                 : "r"(a[0]), "r"(a[1]), "r"(a[2]), "r"(a[3]), "r"(b[0]), "r"(b[1]));
}
// packs {lo=a, hi=b}
__device__ __forceinline__ uint32_t pack_bf(float a, float b) {
    uint32_t r;
    asm("cvt.rn.bf16x2.f32 %0, %1, %2;" : "=r"(r) : "f"(b), "f"(a));
    return r;
}
__device__ __forceinline__ float bf_res(float v) {
    return v - __bfloat162float(__float2bfloat16(v));
}

// ---------------- weight transpose + hi/lo bf16 conversion -------------------
// W[K][N] fp32 -> TH/TL[N][K] bf16
__global__ __launch_bounds__(256) void conv_w(const float* __restrict__ W,
    bf16* __restrict__ TH, bf16* __restrict__ TL, int K, int N)
{
    __shared__ float t[32][33];
    int nt = blockIdx.x * 32, kt = blockIdx.y * 32;
    int tx = threadIdx.x, ty = threadIdx.y;
#pragma unroll
    for (int j = 0; j < 4; j++)
        t[ty + j * 8][tx] = W[(size_t)(kt + ty + j * 8) * N + nt + tx];
    __syncthreads();
#pragma unroll
    for (int j = 0; j < 4; j++) {
        int n = nt + ty + j * 8;
        float v = t[tx][ty + j * 8];
        bf16 h = __float2bfloat16(v);
        TH[(size_t)n * K + kt + tx] = h;
        TL[(size_t)n * K + kt + tx] = __float2bfloat16(v - __bfloat162float(h));
    }
}

// ---------------- LayerNorm -> hi/lo bf16 planes -----------------------------
__global__ __launch_bounds__(256) void ln_kernel(
    const float* __restrict__ x, const float* __restrict__ alpha,
    const float* __restrict__ beta, bf16* __restrict__ outH, bf16* __restrict__ outL)
{
    int row = blockIdx.x;
    const float* xr = x + (size_t)row * DIM_;
    int tid = threadIdx.x;

    float v[4];
    float s = 0.f, s2 = 0.f;
#pragma unroll
    for (int j = 0; j < 4; j++) {
        v[j] = xr[tid + j * 256];
        s += v[j]; s2 += v[j] * v[j];
    }
#pragma unroll
    for (int o = 16; o > 0; o >>= 1) {
        s  += __shfl_xor_sync(0xffffffffu, s,  o);
        s2 += __shfl_xor_sync(0xffffffffu, s2, o);
    }
    __shared__ float rs[8], rs2[8];
    int wid = tid >> 5, lid = tid & 31;
    if (lid == 0) { rs[wid] = s; rs2[wid] = s2; }
    __syncthreads();
    s = 0.f; s2 = 0.f;
#pragma unroll
    for (int i = 0; i < 8; i++) { s += rs[i]; s2 += rs2[i]; }

    float mu  = s * (1.0f / DIM_);
    float var = (s2 - (float)DIM_ * mu * mu) * (1.0f / (DIM_ - 1));
    float inv = 1.0f / (sqrtf(fmaxf(var, 0.f)) + EPSV);
#pragma unroll
    for (int j = 0; j < 4; j++) {
        int c = tid + j * 256;
        float y = alpha[c] * (v[j] - mu) * inv + beta[c];
        bf16 h = __float2bfloat16(y);
        size_t o = (size_t)row * DIM_ + c;
        outH[o] = h;
        outL[o] = __float2bfloat16(y - __bfloat162float(h));
    }
}

// ---------------- HMMA GEMM: C[M,N] = A[M,K] @ Wt[N,K]^T ---------------------
#define PITCH 144
#define PLANE_BYTES (128 * PITCH)              // 18432
#define STAGE_BYTES (4 * PLANE_BYTES)          // 73728
#define GEMM_SMEM   (2 * STAGE_BYTES + 256)

__global__ __launch_bounds__(256, 1)
void gemm_hmma(const bf16* __restrict__ AH, const bf16* __restrict__ AL,
               const bf16* __restrict__ BH, const bf16* __restrict__ BL,
               const float* __restrict__ bias, const float* __restrict__ resid,
               float* __restrict__ Cf, bf16* __restrict__ CH, bf16* __restrict__ CL,
               int M, int N, int K, int relu)
{
    extern __shared__ char dsm[];
    char* sb = (char*)(((uintptr_t)dsm + 127) & ~(uintptr_t)127);
    uint32_t sb32 = smem_u32(sb);

    int tid = threadIdx.x, wid = tid >> 5, lane = tid & 31;
    int rowBase = blockIdx.y * 128, colBase = blockIdx.x * 128;
    int wm = wid & 1, wn = wid >> 1;

    const bf16* planes[4] = {AH, AL, BH, BL};

    float acc[4][4][4];
#pragma unroll
    for (int i = 0; i < 4; i++)
#pragma unroll
        for (int j = 0; j < 4; j++)
#pragma unroll
            for (int q = 0; q < 4; q++) acc[i][j][q] = 0.f;

    uint32_t aRow = (uint32_t)(wm * 64 + (lane & 15));
    uint32_t aCol = (uint32_t)((lane >> 4) * 16);
    uint32_t bRow = (uint32_t)(wn * 32 + (lane & 7));
    uint32_t bCol = (uint32_t)(((lane >> 3) & 1) * 16);

    int NC = K >> 6;

    auto load_stage = [&](int ch, int s) {
        int k0 = ch << 6;
        uint32_t stage = sb32 + s * STAGE_BYTES;
#pragma unroll
        for (int it = 0; it < 16; it++) {
            int idx = it * 256 + tid;
            int pl = idx >> 10;
            int rem = idx & 1023;
            int r = rem >> 3;
            int c = rem & 7;
            int rb = (pl < 2) ? rowBase : colBase;
            const bf16* src = planes[pl] + (size_t)(rb + r) * K + k0 + c * 8;
            uint32_t dst = stage + pl * PLANE_BYTES + r * PITCH + c * 16;
            cp_async16(dst, src);
        }
        cp_commit();
    };

    load_stage(0, 0);

    for (int ch = 0; ch < NC; ch++) {
        int s = ch & 1;
        if (ch + 1 < NC) { load_stage(ch + 1, s ^ 1); cp_wait<1>(); }
        else             { cp_wait<0>(); }
        __syncthreads();

        uint32_t stage = sb32 + s * STAGE_BYTES;
        uint32_t aBaseH = stage + 0 * PLANE_BYTES + aRow * PITCH + aCol;
        uint32_t aBaseL = stage + 1 * PLANE_BYTES + aRow * PITCH + aCol;
        uint32_t bBaseH = stage + 2 * PLANE_BYTES + bRow * PITCH + bCol;
        uint32_t bBaseL = stage + 3 * PLANE_BYTES + bRow * PITCH + bCol;

#pragma unroll
        for (int ks = 0; ks < 4; ks++) {
            uint32_t kOff = ks * 32;
            uint32_t aF[2][4][4], bF[2][4][2];
#pragma unroll
            for (int mt = 0; mt < 4; mt++) {
                ldm_x4(aF[0][mt][0], aF[0][mt][1], aF[0][mt][2], aF[0][mt][3],
                       aBaseH + mt * (16 * PITCH) + kOff);
                ldm_x4(aF[1][mt][0], aF[1][mt][1], aF[1][mt][2], aF[1][mt][3],
                       aBaseL + mt * (16 * PITCH) + kOff);
            }
#pragma unroll
            for (int nt = 0; nt < 4; nt++) {
                ldm_x2(bF[0][nt][0], bF[0][nt][1], bBaseH + nt * (8 * PITCH) + kOff);
                ldm_x2(bF[1][nt][0], bF[1][nt][1], bBaseL + nt * (8 * PITCH) + kOff);
            }
#pragma unroll
            for (int mt = 0; mt < 4; mt++)
#pragma unroll
                for (int nt = 0; nt < 4; nt++) {
                    mma_bf16(acc[mt][nt], aF[0][mt], bF[0][nt]);
                    mma_bf16(acc[mt][nt], aF[0][mt], bF[1][nt]);
                    mma_bf16(acc[mt][nt], aF[1][mt], bF[0][nt]);
                }
        }
        __syncthreads();
    }

    int tr = lane >> 2;
    int tc = (lane & 3) * 2;
#pragma unroll
    for (int mt = 0; mt < 4; mt++) {
#pragma unroll
        for (int half = 0; half < 2; half++) {
            int r = rowBase + wm * 64 + mt * 16 + tr + half * 8;
#pragma unroll
            for (int nt = 0; nt < 4; nt++) {
                int cg = colBase + wn * 32 + nt * 8 + tc;
                size_t off = (size_t)r * N + cg;
                float v0 = acc[mt][nt][half * 2 + 0];
                float v1 = acc[mt][nt][half * 2 + 1];
                if (bias)  { v0 += bias[cg]; v1 += bias[cg + 1]; }
                if (relu)  { v0 = fmaxf(v0, 0.f); v1 = fmaxf(v1, 0.f); }
                if (resid) { v0 += resid[off]; v1 += resid[off + 1]; }
                if (Cf) {
                    float2 o2 = make_float2(v0, v1);
                    *(float2*)&Cf[off] = o2;
                }
                if (CH) {
                    bf16 h0 = __float2bfloat16(v0);
                    bf16 h1 = __float2bfloat16(v1);
                    __nv_bfloat162 hp; hp.x = h0; hp.y = h1;
                    *(__nv_bfloat162*)&CH[off] = hp;
                    __nv_bfloat162 lp;
                    lp.x = __float2bfloat16(v0 - __bfloat162float(h0));
                    lp.y = __float2bfloat16(v1 - __bfloat162float(h1));
                    *(__nv_bfloat162*)&CL[off] = lp;
                }
            }
        }
    }
}

// ---------------- HMMA flash attention ---------------------------------------
// QKV combined layout: [M][3072], q cols 0..1023 (h*64+d), k +1024, v +2048.
// Block: 128 threads (4 warps), 64 q-rows; loop 64-key chunks.
#define AT_PITCH 144
#define AT_PLANE (64 * AT_PITCH)     // 9216
#define ATTN_SMEM (6 * AT_PLANE + 256)

__global__ __launch_bounds__(128, 1) void attn_mma(
    const bf16* __restrict__ QKVH, const bf16* __restrict__ QKVL,
    bf16* __restrict__ OH, bf16* __restrict__ OL)
{
    extern __shared__ char sm_[];
    char* base = (char*)(((uintptr_t)sm_ + 127) & ~(uintptr_t)127);
    uint32_t sb = smem_u32(base);
    uint32_t qhS = sb,               qlS = sb + AT_PLANE;
    uint32_t khS = sb + 2*AT_PLANE,  klS = sb + 3*AT_PLANE;
    uint32_t vhS = sb + 4*AT_PLANE,  vlS = sb + 5*AT_PLANE;

    int tid = threadIdx.x, warp = tid >> 5, lane = tid & 31;
    int qt = blockIdx.x, bh = blockIdx.y;
    int b = bh >> 4, h = bh & 15;
    int qrow0 = b * S_ + qt * 64;

    int lrow = tid >> 1;            // 0..63
    int lseg = (tid & 1) * 32;      // bf16 offset

    // ---- load Q tile (hi/lo) ----
    {
        size_t g = (size_t)(qrow0 + lrow) * (3 * DIM_) + h * HD_ + lseg;
        uint32_t d = lrow * AT_PITCH + lseg * 2;
#pragma unroll
        for (int c = 0; c < 4; c++) cp_async16(qhS + d + c * 16, QKVH + g + c * 8);
#pragma unroll
        for (int c = 0; c < 4; c++) cp_async16(qlS + d + c * 16, QKVL + g + c * 8);
    }
    cp_commit();
    cp_wait<0>();
    __syncthreads();

    // ---- preload Q fragments (4 k-steps, hi+lo) ----
    uint32_t qfH[4][4], qfL[4][4];
    {
        uint32_t aAddr = (uint32_t)(warp * 16 + (lane & 15)) * AT_PITCH + ((lane >> 4) * 16);
#pragma unroll
        for (int ks = 0; ks < 4; ks++) {
            ldm_x4(qfH[ks][0], qfH[ks][1], qfH[ks][2], qfH[ks][3], qhS + aAddr + ks * 32);
            ldm_x4(qfL[ks][0], qfL[ks][1], qfL[ks][2], qfL[ks][3], qlS + aAddr + ks * 32);
        }
    }

    float oacc[8][4];
#pragma unroll
    for (int i = 0; i < 8; i++)
#pragma unroll
        for (int j = 0; j < 4; j++) oacc[i][j] = 0.f;
    float m0 = -1e30f, m1 = -1e30f, l0 = 0.f, l1 = 0.f;

    // B-frag x4 addressing (shared by S pass)
    uint32_t bAddrBase = (uint32_t)(((lane >> 4) & 1) * 8 + (lane & 7)) * AT_PITCH
                       + ((lane >> 3) & 1) * 16;

    for (int kt = 0; kt < S_ / 64; kt++) {
        __syncthreads();
        // ---- load K/V chunk (hi/lo) ----
        {
            size_t gk = (size_t)(b * S_ + kt * 64 + lrow) * (3 * DIM_) + DIM_ + h * HD_ + lseg;
            size_t gv = gk + DIM_;
            uint32_t d = lrow * AT_PITCH + lseg * 2;
#pragma unroll
            for (int c = 0; c < 4; c++) cp_async16(khS + d + c * 16, QKVH + gk + c * 8);
#pragma unroll
            for (int c = 0; c < 4; c++) cp_async16(klS + d + c * 16, QKVL + gk + c * 8);
#pragma unroll
            for (int c = 0; c < 4; c++) cp_async16(vhS + d + c * 16, QKVH + gv + c * 8);
#pragma unroll
            for (int c = 0; c < 4; c++) cp_async16(vlS + d + c * 16, QKVL + gv + c * 8);
        }
        cp_commit();
        cp_wait<0>();
        __syncthreads();

        // ---- S = Q K^T (3-pass hi/lo) ----
        float sacc[8][4];
#pragma unroll
        for (int i = 0; i < 8; i++)
#pragma unroll
            for (int j = 0; j < 4; j++) sacc[i][j] = 0.f;

#pragma unroll
        for (int ks = 0; ks < 4; ks++) {
#pragma unroll
            for (int ntp = 0; ntp < 4; ntp++) {
                uint32_t addr = bAddrBase + (uint32_t)(ntp * 16) * AT_PITCH + ks * 32;
                uint32_t bh4[4], bl4[4];
                ldm_x4(bh4[0], bh4[1], bh4[2], bh4[3], khS + addr);
                ldm_x4(bl4[0], bl4[1], bl4[2], bl4[3], klS + addr);
                mma_bf16(sacc[2*ntp],   qfH[ks], bh4 + 0);
                mma_bf16(sacc[2*ntp],   qfH[ks], bl4 + 0);
                mma_bf16(sacc[2*ntp],   qfL[ks], bh4 + 0);
                mma_bf16(sacc[2*ntp+1], qfH[ks], bh4 + 2);
                mma_bf16(sacc[2*ntp+1], qfH[ks], bl4 + 2);
                mma_bf16(sacc[2*ntp+1], qfL[ks], bh4 + 2);
            }
        }

        // ---- online softmax on fragments ----
        float mx0 = -1e30f, mx1 = -1e30f;
#pragma unroll
        for (int nt = 0; nt < 8; nt++) {
#pragma unroll
            for (int j = 0; j < 4; j++) sacc[nt][j] *= 0.125f;
            mx0 = fmaxf(mx0, fmaxf(sacc[nt][0], sacc[nt][1]));
            mx1 = fmaxf(mx1, fmaxf(sacc[nt][2], sacc[nt][3]));
        }
        mx0 = fmaxf(mx0, __shfl_xor_sync(0xffffffffu, mx0, 1));
        mx0 = fmaxf(mx0, __shfl_xor_sync(0xffffffffu, mx0, 2));
        mx1 = fmaxf(mx1, __shfl_xor_sync(0xffffffffu, mx1, 1));
        mx1 = fmaxf(mx1, __shfl_xor_sync(0xffffffffu, mx1, 2));

        float nm0 = fmaxf(m0, mx0), nm1 = fmaxf(m1, mx1);
        float corr0 = __expf(m0 - nm0), corr1 = __expf(m1 - nm1);
        float rs0 = 0.f, rs1 = 0.f;
#pragma unroll
        for (int nt = 0; nt < 8; nt++) {
            sacc[nt][0] = __expf(sacc[nt][0] - nm0);
            sacc[nt][1] = __expf(sacc[nt][1] - nm0);
            sacc[nt][2] = __expf(sacc[nt][2] - nm1);
            sacc[nt][3] = __expf(sacc[nt][3] - nm1);
            rs0 += sacc[nt][0] + sacc[nt][1];
            rs1 += sacc[nt][2] + sacc[nt][3];
        }
        rs0 += __shfl_xor_sync(0xffffffffu, rs0, 1);
        rs0 += __shfl_xor_sync(0xffffffffu, rs0, 2);
        rs1 += __shfl_xor_sync(0xffffffffu, rs1, 1);
        rs1 += __shfl_xor_sync(0xffffffffu, rs1, 2);
        l0 = l0 * corr0 + rs0;  m0 = nm0;
        l1 = l1 * corr1 + rs1;  m1 = nm1;
#pragma unroll
        for (int nt = 0; nt < 8; nt++) {
            oacc[nt][0] *= corr0; oacc[nt][1] *= corr0;
            oacc[nt][2] *= corr1; oacc[nt][3] *= corr1;
        }

        // ---- O += P V (3-pass: Ph*Vh + Ph*Vl + Pl*Vh) ----
#pragma unroll
        for (int ks = 0; ks < 4; ks++) {
            uint32_t aH[4], aL[4];
            float* se = sacc[2*ks];
            float* so = sacc[2*ks + 1];
            aH[0] = pack_bf(se[0], se[1]);
            aH[1] = pack_bf(se[2], se[3]);
            aH[2] = pack_bf(so[0], so[1]);
            aH[3] = pack_bf(so[2], so[3]);
            aL[0] = pack_bf(bf_res(se[0]), bf_res(se[1]));
            aL[1] = pack_bf(bf_res(se[2]), bf_res(se[3]));
            aL[2] = pack_bf(bf_res(so[0]), bf_res(so[1]));
            aL[3] = pack_bf(bf_res(so[2]), bf_res(so[3]));
#pragma unroll
            for (int ntp = 0; ntp < 4; ntp++) {
                uint32_t addr = (uint32_t)(ks * 16 + (lane & 15)) * AT_PITCH
                              + (uint32_t)(ntp * 2 + ((lane >> 4) & 1)) * 16;
                uint32_t vh4[4], vl4[4];
                ldm_x4t(vh4[0], vh4[1], vh4[2], vh4[3], vhS + addr);
                ldm_x4t(vl4[0], vl4[1], vl4[2], vl4[3], vlS + addr);
                mma_bf16(oacc[2*ntp],   aH, vh4 + 0);
                mma_bf16(oacc[2*ntp],   aH, vl4 + 0);
                mma_bf16(oacc[2*ntp],   aL, vh4 + 0);
                mma_bf16(oacc[2*ntp+1], aH, vh4 + 2);
                mma_bf16(oacc[2*ntp+1], aH, vl4 + 2);
                mma_bf16(oacc[2*ntp+1], aL, vh4 + 2);
            }
        }
    }

    // ---- normalize + write out (bf16 hi/lo planes) ----
    float inv0 = 1.f / l0, inv1 = 1.f / l1;
    int r0g = qrow0 + warp * 16 + (lane >> 2);
    int cbase = h * HD_ + (lane & 3) * 2;
#pragma unroll
    for (int nt = 0; nt < 8; nt++) {
        float v0 = oacc[nt][0] * inv0, v1 = oacc[nt][1] * inv0;
        float v2 = oacc[nt][2] * inv1, v3 = oacc[nt][3] * inv1;
        size_t off0 = (size_t)r0g * DIM_ + cbase + nt * 8;
        size_t off1 = off0 + (size_t)8 * DIM_;
        *(uint32_t*)&OH[off0] = pack_bf(v0, v1);
        *(uint32_t*)&OL[off0] = pack_bf(bf_res(v0), bf_res(v1));
        *(uint32_t*)&OH[off1] = pack_bf(v2, v3);
        *(uint32_t*)&OL[off1] = pack_bf(bf_res(v2), bf_res(v3));
    }
}

// ---------------- launcher ---------------------------------------------------
extern "C" void kernel_launch(void* const* d_in, const int* in_sizes, int n_in,
                              void* d_out, int out_size)
{
    const float* x      = (const float*)d_in[0];
    const float* wq     = (const float*)d_in[2];
    const float* wk     = (const float*)d_in[3];
    const float* wv     = (const float*)d_in[4];
    const float* wo     = (const float*)d_in[5];
    const float* w_up   = (const float*)d_in[6];
    const float* b_up   = (const float*)d_in[7];
    const float* w_down = (const float*)d_in[8];
    const float* b_down = (const float*)d_in[9];
    const float* ln1_a  = (const float*)d_in[10];
    const float* ln1_b  = (const float*)d_in[11];
    const float* ln2_a  = (const float*)d_in[12];
    const float* ln2_b  = (const float*)d_in[13];
    float* out = (float*)d_out;

    bf16 *lnH, *lnL, *qkvH, *qkvL, *atH, *atL, *ffH, *ffL;
    bf16 *wqkvH, *wqkvL, *woH, *woL, *upH, *upL, *dnH, *dnL;
    float *px1;
    cudaGetSymbolAddress((void**)&lnH,   g_lnH);   cudaGetSymbolAddress((void**)&lnL,   g_lnL);
    cudaGetSymbolAddress((void**)&qkvH,  g_qkvH);  cudaGetSymbolAddress((void**)&qkvL,  g_qkvL);
    cudaGetSymbolAddress((void**)&atH,   g_atH);   cudaGetSymbolAddress((void**)&atL,   g_atL);
    cudaGetSymbolAddress((void**)&ffH,   g_ffH);   cudaGetSymbolAddress((void**)&ffL,   g_ffL);
    cudaGetSymbolAddress((void**)&wqkvH, g_wqkvH); cudaGetSymbolAddress((void**)&wqkvL, g_wqkvL);
    cudaGetSymbolAddress((void**)&woH,   g_woH);   cudaGetSymbolAddress((void**)&woL,   g_woL);
    cudaGetSymbolAddress((void**)&upH,   g_upH);   cudaGetSymbolAddress((void**)&upL,   g_upL);
    cudaGetSymbolAddress((void**)&dnH,   g_dnH);   cudaGetSymbolAddress((void**)&dnL,   g_dnL);
    cudaGetSymbolAddress((void**)&px1,   g_x1);

    cudaFuncSetAttribute(gemm_hmma, cudaFuncAttributeMaxDynamicSharedMemorySize, GEMM_SMEM);
    cudaFuncSetAttribute(attn_mma, cudaFuncAttributeMaxDynamicSharedMemorySize, ATTN_SMEM);

    dim3 cblk(32, 8);
    // packed transposed QKV weight [3*DIM][DIM]
    conv_w<<<dim3(DIM_/32, DIM_/32), cblk>>>(wq, wqkvH,                wqkvL,                DIM_, DIM_);
    conv_w<<<dim3(DIM_/32, DIM_/32), cblk>>>(wk, wqkvH + DIM_*DIM_,    wqkvL + DIM_*DIM_,    DIM_, DIM_);
    conv_w<<<dim3(DIM_/32, DIM_/32), cblk>>>(wv, wqkvH + 2*DIM_*DIM_,  wqkvL + 2*DIM_*DIM_,  DIM_, DIM_);
    conv_w<<<dim3(DIM_/32, DIM_/32), cblk>>>(wo, woH, woL, DIM_, DIM_);
    conv_w<<<dim3(DFF_/32, DIM_/32), cblk>>>(w_up, upH, upL, DIM_, DFF_);
    conv_w<<<dim3(DIM_/32, DFF_/32), cblk>>>(w_down, dnH, dnL, DFF_, DIM_);

    dim3 blk(256);
    dim3 gD(DIM_/128, M_/128);
    dim3 gQKV(3*DIM_/128, M_/128);
    dim3 gF(DFF_/128, M_/128);

    // h = LN1(x)
    ln_kernel<<<M_, blk>>>(x, ln1_a, ln1_b, lnH, lnL);
    // fused QKV projection -> bf16 hi/lo planes [M][3072]
    gemm_hmma<<<gQKV, blk, GEMM_SMEM>>>(lnH, lnL, wqkvH, wqkvL, nullptr, nullptr,
                                        nullptr, qkvH, qkvL, M_, 3*DIM_, DIM_, 0);
    // HMMA flash attention -> hi/lo planes
    attn_mma<<<dim3(S_/64, B_*NH_), dim3(128), ATTN_SMEM>>>(qkvH, qkvL, atH, atL);
    // x1 = x + attn @ wo
    gemm_hmma<<<gD, blk, GEMM_SMEM>>>(atH, atL, woH, woL, nullptr, x,
                                      px1, nullptr, nullptr, M_, DIM_, DIM_, 0);
    // h = LN2(x1)
    ln_kernel<<<M_, blk>>>(px1, ln2_a, ln2_b, lnH, lnL);
    // ff = relu(h @ w_up + b_up)
    gemm_hmma<<<gF, blk, GEMM_SMEM>>>(lnH, lnL, upH, upL, b_up, nullptr,
                                      nullptr, ffH, ffL, M_, DFF_, DIM_, 1);
    // out = x1 + ff @ w_down + b_down
    gemm_hmma<<<gD, blk, GEMM_SMEM>>>(ffH, ffL, dnH, dnL, b_down, px1,
                                      out, nullptr, nullptr, M_, DIM_, DFF_, 0);
}

// round 8
// speedup vs baseline: 6.4383x; 2.2541x over previous
#include <cuda_runtime.h>
#include <cuda_fp16.h>
#include <cstdint>
#include <math.h>

// Problem constants
#define B_   2
#define S_   2048
#define M_   (B_*S_)      // 4096 rows
#define DIM_ 1024
#define DFF_ 4096
#define NH_  16
#define HD_  64
#define EPSV 1e-6f

typedef __half f16;

// ---------------- scratch (device globals; no allocations allowed) ----------
__device__ __align__(16) f16   g_ln  [M_*DIM_];
__device__ __align__(16) f16   g_qkv [(size_t)M_*3*DIM_];
__device__ __align__(16) f16   g_at  [M_*DIM_];
__device__ __align__(16) float g_x1  [M_*DIM_];
__device__ __align__(16) f16   g_ff  [(size_t)M_*DFF_];
// transposed fp16 weights, layout [N][K]
__device__ __align__(16) f16   g_wqkv[(size_t)3*DIM_*DIM_];
__device__ __align__(16) f16   g_wo  [DIM_*DIM_];
__device__ __align__(16) f16   g_up  [(size_t)DFF_*DIM_];
__device__ __align__(16) f16   g_dn  [(size_t)DIM_*DFF_];

// ---------------- PTX helpers ------------------------------------------------
__device__ __forceinline__ uint32_t smem_u32(const void* p) {
    uint32_t a;
    asm("{ .reg .u64 t; cvta.to.shared.u64 t, %1; cvt.u32.u64 %0, t; }" : "=r"(a) : "l"(p));
    return a;
}
__device__ __forceinline__ void cp_async16(uint32_t saddr, const void* gaddr) {
    asm volatile("cp.async.cg.shared.global [%0], [%1], 16;" :: "r"(saddr), "l"(gaddr) : "memory");
}
__device__ __forceinline__ void cp_commit() {
    asm volatile("cp.async.commit_group;" ::: "memory");
}
template<int N>
__device__ __forceinline__ void cp_wait() {
    asm volatile("cp.async.wait_group %0;" :: "n"(N) : "memory");
}
__device__ __forceinline__ void ldm_x4(uint32_t& r0, uint32_t& r1, uint32_t& r2, uint32_t& r3,
                                       uint32_t addr) {
    asm volatile("ldmatrix.sync.aligned.m8n8.x4.shared.b16 {%0,%1,%2,%3}, [%4];"
                 : "=r"(r0), "=r"(r1), "=r"(r2), "=r"(r3) : "r"(addr));
}
__device__ __forceinline__ void ldm_x4t(uint32_t& r0, uint32_t& r1, uint32_t& r2, uint32_t& r3,
                                        uint32_t addr) {
    asm volatile("ldmatrix.sync.aligned.m8n8.x4.trans.shared.b16 {%0,%1,%2,%3}, [%4];"
                 : "=r"(r0), "=r"(r1), "=r"(r2), "=r"(r3) : "r"(addr));
}
__device__ __forceinline__ void mma_f16(float* c, const uint32_t* a, const uint32_t* b) {
    asm volatile("mma.sync.aligned.m16n8k16.row.col.f32.f16.f16.f32 "
                 "{%0,%1,%2,%3}, {%4,%5,%6,%7}, {%8,%9}, {%0,%1,%2,%3};"
                 : "+f"(c[0]), "+f"(c[1]), "+f"(c[2]), "+f"(c[3])
                 : "r"(a[0]), "r"(a[1]), "r"(a[2]), "r"(a[3]), "r"(b[0]), "r"(b[1]));
}
// packs {lo=a, hi=b}
__device__ __forceinline__ uint32_t pack_f16(float a, float b) {
    uint32_t r;
    asm("cvt.rn.f16x2.f32 %0, %1, %2;" : "=r"(r) : "f"(b), "f"(a));
    return r;
}

// ---------------- weight transpose + fp16 conversion -------------------------
// W[K][N] fp32 -> T[N][K] fp16
__global__ __launch_bounds__(256) void conv_w(const float* __restrict__ W,
    f16* __restrict__ T, int K, int N)
{
    __shared__ float t[32][33];
    int nt = blockIdx.x * 32, kt = blockIdx.y * 32;
    int tx = threadIdx.x, ty = threadIdx.y;
#pragma unroll
    for (int j = 0; j < 4; j++)
        t[ty + j * 8][tx] = W[(size_t)(kt + ty + j * 8) * N + nt + tx];
    __syncthreads();
#pragma unroll
    for (int j = 0; j < 4; j++) {
        int n = nt + ty + j * 8;
        T[(size_t)n * K + kt + tx] = __float2half_rn(t[tx][ty + j * 8]);
    }
}

// ---------------- LayerNorm -> fp16 ------------------------------------------
__global__ __launch_bounds__(256) void ln_kernel(
    const float* __restrict__ x, const float* __restrict__ alpha,
    const float* __restrict__ beta, f16* __restrict__ outp)
{
    int row = blockIdx.x;
    const float* xr = x + (size_t)row * DIM_;
    int tid = threadIdx.x;

    float v[4];
    float s = 0.f, s2 = 0.f;
#pragma unroll
    for (int j = 0; j < 4; j++) {
        v[j] = xr[tid + j * 256];
        s += v[j]; s2 += v[j] * v[j];
    }
#pragma unroll
    for (int o = 16; o > 0; o >>= 1) {
        s  += __shfl_xor_sync(0xffffffffu, s,  o);
        s2 += __shfl_xor_sync(0xffffffffu, s2, o);
    }
    __shared__ float rs[8], rs2[8];
    int wid = tid >> 5, lid = tid & 31;
    if (lid == 0) { rs[wid] = s; rs2[wid] = s2; }
    __syncthreads();
    s = 0.f; s2 = 0.f;
#pragma unroll
    for (int i = 0; i < 8; i++) { s += rs[i]; s2 += rs2[i]; }

    float mu  = s * (1.0f / DIM_);
    float var = (s2 - (float)DIM_ * mu * mu) * (1.0f / (DIM_ - 1));
    float inv = 1.0f / (sqrtf(fmaxf(var, 0.f)) + EPSV);
#pragma unroll
    for (int j = 0; j < 4; j++) {
        int c = tid + j * 256;
        float y = alpha[c] * (v[j] - mu) * inv + beta[c];
        outp[(size_t)row * DIM_ + c] = __float2half_rn(y);
    }
}

// ---------------- HMMA fp16 GEMM: C[M,N] = A[M,K] @ Wt[N,K]^T ----------------
// CTA tile 128x256, 8 warps (64x64 each), K-chunk 64, 2-stage cp.async.
#define PITCH 144
#define A_BYTES (128 * PITCH)                 // 18432
#define B_BYTES (256 * PITCH)                 // 36864
#define STAGE_BYTES (A_BYTES + B_BYTES)       // 55296
#define GEMM_SMEM   (2 * STAGE_BYTES + 256)

__global__ __launch_bounds__(256, 1)
void gemm_f16(const f16* __restrict__ A, const f16* __restrict__ Bw,
              const float* __restrict__ bias, const float* __restrict__ resid,
              float* __restrict__ Cf, f16* __restrict__ Ch,
              int M, int N, int K, int relu)
{
    extern __shared__ char dsm[];
    char* sb = (char*)(((uintptr_t)dsm + 127) & ~(uintptr_t)127);
    uint32_t sb32 = smem_u32(sb);

    int tid = threadIdx.x, wid = tid >> 5, lane = tid & 31;
    int rowBase = blockIdx.y * 128, colBase = blockIdx.x * 256;
    int wm = wid & 1, wn = wid >> 1;     // warp tile: rows wm*64, cols wn*64

    float acc[4][8][4];
#pragma unroll
    for (int i = 0; i < 4; i++)
#pragma unroll
        for (int j = 0; j < 8; j++)
#pragma unroll
            for (int q = 0; q < 4; q++) acc[i][j][q] = 0.f;

    // A x4 frag addressing: rows lane&15, col halves by lane>>4
    uint32_t aOff = (uint32_t)(wm * 64 + (lane & 15)) * PITCH + (uint32_t)((lane >> 4) * 16);
    // B x4 frag addressing (n8k16 pairs): rows ((lane>>4)&1)*8 + (lane&7),
    // col halves by (lane>>3)&1  ->  frags {n0-7 k0-7, n0-7 k8-15, n8-15 k0-7, n8-15 k8-15}
    uint32_t bOff = (uint32_t)(wn * 64 + ((lane >> 4) & 1) * 8 + (lane & 7)) * PITCH
                  + (uint32_t)(((lane >> 3) & 1) * 16) + A_BYTES;

    int NC = K >> 6;

    // stage loader: A 128x8 + B 256x8 16B chunks = 3072 transfers (12 iters x 256 thr)
    auto load_stage = [&](int ch, int s) {
        int k0 = ch << 6;
        uint32_t stage = sb32 + s * STAGE_BYTES;
#pragma unroll
        for (int it = 0; it < 12; it++) {
            int idx = it * 256 + tid;
            if (idx < 1024) {
                int r = idx >> 3, c = idx & 7;
                cp_async16(stage + r * PITCH + c * 16,
                           A + (size_t)(rowBase + r) * K + k0 + c * 8);
            } else {
                int rem = idx - 1024;
                int r = rem >> 3, c = rem & 7;
                cp_async16(stage + A_BYTES + r * PITCH + c * 16,
                           Bw + (size_t)(colBase + r) * K + k0 + c * 8);
            }
        }
        cp_commit();
    };

    load_stage(0, 0);

    for (int ch = 0; ch < NC; ch++) {
        int s = ch & 1;
        if (ch + 1 < NC) { load_stage(ch + 1, s ^ 1); cp_wait<1>(); }
        else             { cp_wait<0>(); }
        __syncthreads();

        uint32_t stage = sb32 + s * STAGE_BYTES;
        uint32_t aBase = stage + aOff;
        uint32_t bBase = stage + bOff;

#pragma unroll
        for (int ks = 0; ks < 4; ks++) {
            uint32_t kOff = ks * 32;
            uint32_t aF[4][4], bF[4][4];
#pragma unroll
            for (int mt = 0; mt < 4; mt++)
                ldm_x4(aF[mt][0], aF[mt][1], aF[mt][2], aF[mt][3],
                       aBase + mt * (16 * PITCH) + kOff);
#pragma unroll
            for (int ntp = 0; ntp < 4; ntp++)
                ldm_x4(bF[ntp][0], bF[ntp][1], bF[ntp][2], bF[ntp][3],
                       bBase + ntp * (16 * PITCH) + kOff);
#pragma unroll
            for (int mt = 0; mt < 4; mt++)
#pragma unroll
                for (int ntp = 0; ntp < 4; ntp++) {
                    mma_f16(acc[mt][2*ntp],   aF[mt], bF[ntp] + 0);
                    mma_f16(acc[mt][2*ntp+1], aF[mt], bF[ntp] + 2);
                }
        }
        __syncthreads();
    }

    // epilogue
    int tr = lane >> 2;
    int tc = (lane & 3) * 2;
#pragma unroll
    for (int mt = 0; mt < 4; mt++) {
#pragma unroll
        for (int half = 0; half < 2; half++) {
            int r = rowBase + wm * 64 + mt * 16 + tr + half * 8;
#pragma unroll
            for (int nt = 0; nt < 8; nt++) {
                int cg = colBase + wn * 64 + nt * 8 + tc;
                size_t off = (size_t)r * N + cg;
                float v0 = acc[mt][nt][half * 2 + 0];
                float v1 = acc[mt][nt][half * 2 + 1];
                if (bias)  { v0 += bias[cg]; v1 += bias[cg + 1]; }
                if (relu)  { v0 = fmaxf(v0, 0.f); v1 = fmaxf(v1, 0.f); }
                if (resid) { v0 += resid[off]; v1 += resid[off + 1]; }
                if (Cf) *(float2*)&Cf[off] = make_float2(v0, v1);
                if (Ch) *(uint32_t*)&Ch[off] = pack_f16(v0, v1);
            }
        }
    }
}

// ---------------- HMMA fp16 flash attention ----------------------------------
// QKV layout [M][3072]: q = h*64+d, k = +1024, v = +2048.
// 128 threads (4 warps), 64 q-rows, 64-key chunks.
#define AT_PITCH 144
#define AT_PLANE (64 * AT_PITCH)     // 9216
#define ATTN_SMEM (3 * AT_PLANE + 256)

__global__ __launch_bounds__(128) void attn_mma(
    const f16* __restrict__ QKV, f16* __restrict__ O)
{
    extern __shared__ char sm_[];
    char* base = (char*)(((uintptr_t)sm_ + 127) & ~(uintptr_t)127);
    uint32_t sb = smem_u32(base);
    uint32_t qS = sb, kS = sb + AT_PLANE, vS = sb + 2 * AT_PLANE;

    int tid = threadIdx.x, warp = tid >> 5, lane = tid & 31;
    int qt = blockIdx.x, bh = blockIdx.y;
    int b = bh >> 4, h = bh & 15;
    int qrow0 = b * S_ + qt * 64;

    int lrow = tid >> 1;            // 0..63
    int lseg = (tid & 1) * 32;

    // ---- load Q tile ----
    {
        size_t g = (size_t)(qrow0 + lrow) * (3 * DIM_) + h * HD_ + lseg;
        uint32_t d = lrow * AT_PITCH + lseg * 2;
#pragma unroll
        for (int c = 0; c < 4; c++) cp_async16(qS + d + c * 16, QKV + g + c * 8);
    }
    cp_commit();
    cp_wait<0>();
    __syncthreads();

    // ---- preload Q fragments ----
    uint32_t qf[4][4];
    {
        uint32_t aAddr = (uint32_t)(warp * 16 + (lane & 15)) * AT_PITCH + ((lane >> 4) * 16);
#pragma unroll
        for (int ks = 0; ks < 4; ks++)
            ldm_x4(qf[ks][0], qf[ks][1], qf[ks][2], qf[ks][3], qS + aAddr + ks * 32);
    }

    float oacc[8][4];
#pragma unroll
    for (int i = 0; i < 8; i++)
#pragma unroll
        for (int j = 0; j < 4; j++) oacc[i][j] = 0.f;
    float m0 = -1e30f, m1 = -1e30f, l0 = 0.f, l1 = 0.f;

    uint32_t bAddrBase = (uint32_t)(((lane >> 4) & 1) * 8 + (lane & 7)) * AT_PITCH
                       + ((lane >> 3) & 1) * 16;

    for (int kt = 0; kt < S_ / 64; kt++) {
        __syncthreads();
        {
            size_t gk = (size_t)(b * S_ + kt * 64 + lrow) * (3 * DIM_) + DIM_ + h * HD_ + lseg;
            size_t gv = gk + DIM_;
            uint32_t d = lrow * AT_PITCH + lseg * 2;
#pragma unroll
            for (int c = 0; c < 4; c++) cp_async16(kS + d + c * 16, QKV + gk + c * 8);
#pragma unroll
            for (int c = 0; c < 4; c++) cp_async16(vS + d + c * 16, QKV + gv + c * 8);
        }
        cp_commit();
        cp_wait<0>();
        __syncthreads();

        // ---- S = Q K^T ----
        float sacc[8][4];
#pragma unroll
        for (int i = 0; i < 8; i++)
#pragma unroll
            for (int j = 0; j < 4; j++) sacc[i][j] = 0.f;

#pragma unroll
        for (int ks = 0; ks < 4; ks++) {
#pragma unroll
            for (int ntp = 0; ntp < 4; ntp++) {
                uint32_t addr = bAddrBase + (uint32_t)(ntp * 16) * AT_PITCH + ks * 32;
                uint32_t b4[4];
                ldm_x4(b4[0], b4[1], b4[2], b4[3], kS + addr);
                mma_f16(sacc[2*ntp],   qf[ks], b4 + 0);
                mma_f16(sacc[2*ntp+1], qf[ks], b4 + 2);
            }
        }

        // ---- online softmax ----
        float mx0 = -1e30f, mx1 = -1e30f;
#pragma unroll
        for (int nt = 0; nt < 8; nt++) {
#pragma unroll
            for (int j = 0; j < 4; j++) sacc[nt][j] *= 0.125f;
            mx0 = fmaxf(mx0, fmaxf(sacc[nt][0], sacc[nt][1]));
            mx1 = fmaxf(mx1, fmaxf(sacc[nt][2], sacc[nt][3]));
        }
        mx0 = fmaxf(mx0, __shfl_xor_sync(0xffffffffu, mx0, 1));
        mx0 = fmaxf(mx0, __shfl_xor_sync(0xffffffffu, mx0, 2));
        mx1 = fmaxf(mx1, __shfl_xor_sync(0xffffffffu, mx1, 1));
        mx1 = fmaxf(mx1, __shfl_xor_sync(0xffffffffu, mx1, 2));

        float nm0 = fmaxf(m0, mx0), nm1 = fmaxf(m1, mx1);
        float corr0 = __expf(m0 - nm0), corr1 = __expf(m1 - nm1);
        float rs0 = 0.f, rs1 = 0.f;
#pragma unroll
        for (int nt = 0; nt < 8; nt++) {
            sacc[nt][0] = __expf(sacc[nt][0] - nm0);
            sacc[nt][1] = __expf(sacc[nt][1] - nm0);
            sacc[nt][2] = __expf(sacc[nt][2] - nm1);
            sacc[nt][3] = __expf(sacc[nt][3] - nm1);
            rs0 += sacc[nt][0] + sacc[nt][1];
            rs1 += sacc[nt][2] + sacc[nt][3];
        }
        rs0 += __shfl_xor_sync(0xffffffffu, rs0, 1);
        rs0 += __shfl_xor_sync(0xffffffffu, rs0, 2);
        rs1 += __shfl_xor_sync(0xffffffffu, rs1, 1);
        rs1 += __shfl_xor_sync(0xffffffffu, rs1, 2);
        l0 = l0 * corr0 + rs0;  m0 = nm0;
        l1 = l1 * corr1 + rs1;  m1 = nm1;
#pragma unroll
        for (int nt = 0; nt < 8; nt++) {
            oacc[nt][0] *= corr0; oacc[nt][1] *= corr0;
            oacc[nt][2] *= corr1; oacc[nt][3] *= corr1;
        }

        // ---- O += P V ----
#pragma unroll
        for (int ks = 0; ks < 4; ks++) {
            uint32_t aP[4];
            float* se = sacc[2*ks];
            float* so = sacc[2*ks + 1];
            aP[0] = pack_f16(se[0], se[1]);
            aP[1] = pack_f16(se[2], se[3]);
            aP[2] = pack_f16(so[0], so[1]);
            aP[3] = pack_f16(so[2], so[3]);
#pragma unroll
            for (int ntp = 0; ntp < 4; ntp++) {
                uint32_t addr = (uint32_t)(ks * 16 + (lane & 15)) * AT_PITCH
                              + (uint32_t)(ntp * 2 + ((lane >> 4) & 1)) * 16;
                uint32_t v4[4];
                ldm_x4t(v4[0], v4[1], v4[2], v4[3], vS + addr);
                mma_f16(oacc[2*ntp],   aP, v4 + 0);
                mma_f16(oacc[2*ntp+1], aP, v4 + 2);
            }
        }
    }

    // ---- normalize + write out ----
    float inv0 = 1.f / l0, inv1 = 1.f / l1;
    int r0g = qrow0 + warp * 16 + (lane >> 2);
    int cbase = h * HD_ + (lane & 3) * 2;
#pragma unroll
    for (int nt = 0; nt < 8; nt++) {
        float v0 = oacc[nt][0] * inv0, v1 = oacc[nt][1] * inv0;
        float v2 = oacc[nt][2] * inv1, v3 = oacc[nt][3] * inv1;
        size_t off0 = (size_t)r0g * DIM_ + cbase + nt * 8;
        size_t off1 = off0 + (size_t)8 * DIM_;
        *(uint32_t*)&O[off0] = pack_f16(v0, v1);
        *(uint32_t*)&O[off1] = pack_f16(v2, v3);
    }
}

// ---------------- launcher ---------------------------------------------------
extern "C" void kernel_launch(void* const* d_in, const int* in_sizes, int n_in,
                              void* d_out, int out_size)
{
    const float* x      = (const float*)d_in[0];
    const float* wq     = (const float*)d_in[2];
    const float* wk     = (const float*)d_in[3];
    const float* wv     = (const float*)d_in[4];
    const float* wo     = (const float*)d_in[5];
    const float* w_up   = (const float*)d_in[6];
    const float* b_up   = (const float*)d_in[7];
    const float* w_down = (const float*)d_in[8];
    const float* b_down = (const float*)d_in[9];
    const float* ln1_a  = (const float*)d_in[10];
    const float* ln1_b  = (const float*)d_in[11];
    const float* ln2_a  = (const float*)d_in[12];
    const float* ln2_b  = (const float*)d_in[13];
    float* out = (float*)d_out;

    f16 *lnp, *qkv, *at, *ff, *wqkvT, *woT, *upT, *dnT;
    float *px1;
    cudaGetSymbolAddress((void**)&lnp,   g_ln);
    cudaGetSymbolAddress((void**)&qkv,   g_qkv);
    cudaGetSymbolAddress((void**)&at,    g_at);
    cudaGetSymbolAddress((void**)&ff,    g_ff);
    cudaGetSymbolAddress((void**)&wqkvT, g_wqkv);
    cudaGetSymbolAddress((void**)&woT,   g_wo);
    cudaGetSymbolAddress((void**)&upT,   g_up);
    cudaGetSymbolAddress((void**)&dnT,   g_dn);
    cudaGetSymbolAddress((void**)&px1,   g_x1);

    cudaFuncSetAttribute(gemm_f16, cudaFuncAttributeMaxDynamicSharedMemorySize, GEMM_SMEM);
    cudaFuncSetAttribute(attn_mma, cudaFuncAttributeMaxDynamicSharedMemorySize, ATTN_SMEM);

    dim3 cblk(32, 8);
    conv_w<<<dim3(DIM_/32, DIM_/32), cblk>>>(wq, wqkvT,               DIM_, DIM_);
    conv_w<<<dim3(DIM_/32, DIM_/32), cblk>>>(wk, wqkvT + DIM_*DIM_,   DIM_, DIM_);
    conv_w<<<dim3(DIM_/32, DIM_/32), cblk>>>(wv, wqkvT + 2*DIM_*DIM_, DIM_, DIM_);
    conv_w<<<dim3(DIM_/32, DIM_/32), cblk>>>(wo, woT, DIM_, DIM_);
    conv_w<<<dim3(DFF_/32, DIM_/32), cblk>>>(w_up, upT, DIM_, DFF_);
    conv_w<<<dim3(DIM_/32, DFF_/32), cblk>>>(w_down, dnT, DFF_, DIM_);

    dim3 blk(256);
    dim3 gD(DIM_/256, M_/128);      // N=1024
    dim3 gQKV(3*DIM_/256, M_/128);  // N=3072
    dim3 gF(DFF_/256, M_/128);      // N=4096

    // h = LN1(x)
    ln_kernel<<<M_, blk>>>(x, ln1_a, ln1_b, lnp);
    // fused QKV projection -> fp16 [M][3072]
    gemm_f16<<<gQKV, blk, GEMM_SMEM>>>(lnp, wqkvT, nullptr, nullptr,
                                       nullptr, qkv, M_, 3*DIM_, DIM_, 0);
    // flash attention -> fp16
    attn_mma<<<dim3(S_/64, B_*NH_), dim3(128), ATTN_SMEM>>>(qkv, at);
    // x1 = x + attn @ wo
    gemm_f16<<<gD, blk, GEMM_SMEM>>>(at, woT, nullptr, x,
                                     px1, nullptr, M_, DIM_, DIM_, 0);
    // h = LN2(x1)
    ln_kernel<<<M_, blk>>>(px1, ln2_a, ln2_b, lnp);
    // ff = relu(h @ w_up + b_up) -> fp16
    gemm_f16<<<gF, blk, GEMM_SMEM>>>(lnp, upT, b_up, nullptr,
                                     nullptr, ff, M_, DFF_, DIM_, 1);
    // out = x1 + ff @ w_down + b_down
    gemm_f16<<<gD, blk, GEMM_SMEM>>>(ff, dnT, b_down, px1,
                                     out, nullptr, M_, DIM_, DFF_, 0);
}

// round 10
// speedup vs baseline: 7.2034x; 1.1188x over previous
#include <cuda_runtime.h>
#include <cuda_fp16.h>
#include <cstdint>
#include <math.h>

// Problem constants
#define B_   2
#define S_   2048
#define M_   (B_*S_)      // 4096 rows
#define DIM_ 1024
#define DFF_ 4096
#define NH_  16
#define HD_  64
#define EPSV 1e-6f

typedef __half f16;

// ---------------- scratch (device globals; no allocations allowed) ----------
__device__ __align__(16) f16   g_ln  [M_*DIM_];
__device__ __align__(16) f16   g_qkv [(size_t)M_*3*DIM_];
__device__ __align__(16) f16   g_at  [M_*DIM_];
__device__ __align__(16) float g_x1  [M_*DIM_];
__device__ __align__(16) f16   g_ff  [(size_t)M_*DFF_];
// fp16 weights in ORIGINAL [K][N] layout (no transpose; B uses ldmatrix.trans)
__device__ __align__(16) f16   g_wqkv[(size_t)DIM_*3*DIM_];   // [1024][3072] (q|k|v)
__device__ __align__(16) f16   g_wo  [DIM_*DIM_];             // [1024][1024]
__device__ __align__(16) f16   g_up  [(size_t)DIM_*DFF_];     // [1024][4096]
__device__ __align__(16) f16   g_dn  [(size_t)DFF_*DIM_];     // [4096][1024]

// ---------------- PTX helpers ------------------------------------------------
__device__ __forceinline__ uint32_t smem_u32(const void* p) {
    uint32_t a;
    asm("{ .reg .u64 t; cvta.to.shared.u64 t, %1; cvt.u32.u64 %0, t; }" : "=r"(a) : "l"(p));
    return a;
}
__device__ __forceinline__ void cp_async16(uint32_t saddr, const void* gaddr) {
    asm volatile("cp.async.cg.shared.global [%0], [%1], 16;" :: "r"(saddr), "l"(gaddr) : "memory");
}
__device__ __forceinline__ void cp_commit() {
    asm volatile("cp.async.commit_group;" ::: "memory");
}
template<int N>
__device__ __forceinline__ void cp_wait() {
    asm volatile("cp.async.wait_group %0;" :: "n"(N) : "memory");
}
__device__ __forceinline__ void ldm_x4(uint32_t& r0, uint32_t& r1, uint32_t& r2, uint32_t& r3,
                                       uint32_t addr) {
    asm volatile("ldmatrix.sync.aligned.m8n8.x4.shared.b16 {%0,%1,%2,%3}, [%4];"
                 : "=r"(r0), "=r"(r1), "=r"(r2), "=r"(r3) : "r"(addr));
}
__device__ __forceinline__ void ldm_x4t(uint32_t& r0, uint32_t& r1, uint32_t& r2, uint32_t& r3,
                                        uint32_t addr) {
    asm volatile("ldmatrix.sync.aligned.m8n8.x4.trans.shared.b16 {%0,%1,%2,%3}, [%4];"
                 : "=r"(r0), "=r"(r1), "=r"(r2), "=r"(r3) : "r"(addr));
}
__device__ __forceinline__ void mma_f16(float* c, const uint32_t* a, const uint32_t* b) {
    asm volatile("mma.sync.aligned.m16n8k16.row.col.f32.f16.f16.f32 "
                 "{%0,%1,%2,%3}, {%4,%5,%6,%7}, {%8,%9}, {%0,%1,%2,%3};"
                 : "+f"(c[0]), "+f"(c[1]), "+f"(c[2]), "+f"(c[3])
                 : "r"(a[0]), "r"(a[1]), "r"(a[2]), "r"(a[3]), "r"(b[0]), "r"(b[1]));
}
// packs {lo=a, hi=b}
__device__ __forceinline__ uint32_t pack_f16(float a, float b) {
    uint32_t r;
    asm("cvt.rn.f16x2.f32 %0, %1, %2;" : "=r"(r) : "f"(b), "f"(a));
    return r;
}

// ---------------- one-shot fp32 -> fp16 weight convert (NO transpose) --------
// units of 4 elems; segments: wq|wk|wv (interleave into [1024][3072]), wo, up, dn
__global__ __launch_bounds__(256) void conv_all(
    const float* __restrict__ wq, const float* __restrict__ wk,
    const float* __restrict__ wv, const float* __restrict__ wo,
    const float* __restrict__ up, const float* __restrict__ dn,
    f16* __restrict__ dqkv, f16* __restrict__ dwo,
    f16* __restrict__ dup, f16* __restrict__ ddn)
{
    size_t t = (size_t)blockIdx.x * 256 + threadIdx.x;   // one float4 per thread
    const float* src;
    f16* dst;
    if (t < 786432) {                        // 3 x 262144 units (wq, wk, wv)
        int seg = (int)(t >> 18);
        size_t e = (t & 262143) * 4;
        int k = (int)(e >> 10), n = (int)(e & 1023);
        src = (seg == 0 ? wq : seg == 1 ? wk : wv) + e;
        dst = dqkv + (size_t)k * 3072 + seg * 1024 + n;
    } else if (t < 1048576) {                // wo: 262144 units
        size_t e = (t - 786432) * 4;
        src = wo + e; dst = dwo + e;
    } else if (t < 2097152) {                // up: 1M units
        size_t e = (t - 1048576) * 4;
        src = up + e; dst = dup + e;
    } else {                                 // dn: 1M units
        size_t e = (t - 2097152) * 4;
        src = dn + e; dst = ddn + e;
    }
    float4 v = *(const float4*)src;
    __half2 h0 = __floats2half2_rn(v.x, v.y);
    __half2 h1 = __floats2half2_rn(v.z, v.w);
    uint2 o;
    o.x = *(uint32_t*)&h0;
    o.y = *(uint32_t*)&h1;
    *(uint2*)dst = o;
}

// ---------------- LayerNorm -> fp16 ------------------------------------------
__global__ __launch_bounds__(256) void ln_kernel(
    const float* __restrict__ x, const float* __restrict__ alpha,
    const float* __restrict__ beta, f16* __restrict__ outp)
{
    int row = blockIdx.x;
    const float* xr = x + (size_t)row * DIM_;
    int tid = threadIdx.x;

    float v[4];
    float s = 0.f, s2 = 0.f;
#pragma unroll
    for (int j = 0; j < 4; j++) {
        v[j] = xr[tid + j * 256];
        s += v[j]; s2 += v[j] * v[j];
    }
#pragma unroll
    for (int o = 16; o > 0; o >>= 1) {
        s  += __shfl_xor_sync(0xffffffffu, s,  o);
        s2 += __shfl_xor_sync(0xffffffffu, s2, o);
    }
    __shared__ float rs[8], rs2[8];
    int wid = tid >> 5, lid = tid & 31;
    if (lid == 0) { rs[wid] = s; rs2[wid] = s2; }
    __syncthreads();
    s = 0.f; s2 = 0.f;
#pragma unroll
    for (int i = 0; i < 8; i++) { s += rs[i]; s2 += rs2[i]; }

    float mu  = s * (1.0f / DIM_);
    float var = (s2 - (float)DIM_ * mu * mu) * (1.0f / (DIM_ - 1));
    float inv = 1.0f / (sqrtf(fmaxf(var, 0.f)) + EPSV);
#pragma unroll
    for (int j = 0; j < 4; j++) {
        int c = tid + j * 256;
        float y = alpha[c] * (v[j] - mu) * inv + beta[c];
        outp[(size_t)row * DIM_ + c] = __float2half_rn(y);
    }
}

// ---------------- HMMA fp16 GEMM: C[M,N] = A[M,K] @ W[K,N] -------------------
// A row-major [M][K]; W row-major [K][N] (B frags via ldmatrix.trans).
// CTA tile 128x256, 8 warps (64x64 each), K-chunk 64, 2-stage cp.async.
#define APITCH 144
#define ABYTES (128 * APITCH)                 // 18432
#define BPITCH 528
#define BBYTES (64 * BPITCH)                  // 33792
#define STAGE_BYTES (ABYTES + BBYTES)         // 52224
#define GEMM_SMEM   (2 * STAGE_BYTES + 256)

__global__ __launch_bounds__(256, 1)
void gemm_f16(const f16* __restrict__ A, const f16* __restrict__ Bw,
              const float* __restrict__ bias, const float* __restrict__ resid,
              float* __restrict__ Cf, f16* __restrict__ Ch,
              int M, int N, int K, int relu)
{
    extern __shared__ char dsm[];
    char* sb = (char*)(((uintptr_t)dsm + 127) & ~(uintptr_t)127);
    uint32_t sb32 = smem_u32(sb);

    int tid = threadIdx.x, wid = tid >> 5, lane = tid & 31;
    int rowBase = blockIdx.y * 128, colBase = blockIdx.x * 256;
    int wm = wid & 1, wn = wid >> 1;     // warp tile: rows wm*64, cols wn*64

    float acc[4][8][4];
#pragma unroll
    for (int i = 0; i < 4; i++)
#pragma unroll
        for (int j = 0; j < 8; j++)
#pragma unroll
            for (int q = 0; q < 4; q++) acc[i][j][q] = 0.f;

    // A x4 frag: rows lane&15, k-halves by lane>>4
    uint32_t aOff = (uint32_t)(wm * 64 + (lane & 15)) * APITCH + (uint32_t)((lane >> 4) * 16);
    // B x4t frag (proven attention-PV pattern): k rows lane&15 (within ks*16),
    // n-halves by (lane>>4)&1; warp n-window = wn*64 cols (128 bytes)
    uint32_t bLane = ABYTES + (uint32_t)(lane & 15) * BPITCH
                   + (uint32_t)(wn * 128) + (uint32_t)(((lane >> 4) & 1) * 16);

    int NC = K >> 6;

    // stage loader: A 128 rows x 8 chunks + B 64 rows x 32 chunks = 3072
    auto load_stage = [&](int ch, int s) {
        int k0 = ch << 6;
        uint32_t stage = sb32 + s * STAGE_BYTES;
#pragma unroll
        for (int it = 0; it < 12; it++) {
            int idx = it * 256 + tid;
            if (idx < 1024) {
                int r = idx >> 3, c = idx & 7;
                cp_async16(stage + r * APITCH + c * 16,
                           A + (size_t)(rowBase + r) * K + k0 + c * 8);
            } else {
                int j = idx - 1024;
                int r = j >> 5, c = j & 31;
                cp_async16(stage + ABYTES + r * BPITCH + c * 16,
                           Bw + (size_t)(k0 + r) * N + colBase + c * 8);
            }
        }
        cp_commit();
    };

    load_stage(0, 0);

    for (int ch = 0; ch < NC; ch++) {
        int s = ch & 1;
        if (ch + 1 < NC) { load_stage(ch + 1, s ^ 1); cp_wait<1>(); }
        else             { cp_wait<0>(); }
        __syncthreads();

        uint32_t stage = sb32 + s * STAGE_BYTES;
        uint32_t aBase = stage + aOff;
        uint32_t bBase = stage + bLane;

#pragma unroll
        for (int ks = 0; ks < 4; ks++) {
            uint32_t aF[4][4], bF[4][4];
#pragma unroll
            for (int mt = 0; mt < 4; mt++)
                ldm_x4(aF[mt][0], aF[mt][1], aF[mt][2], aF[mt][3],
                       aBase + mt * (16 * APITCH) + ks * 32);
#pragma unroll
            for (int ntp = 0; ntp < 4; ntp++)
                ldm_x4t(bF[ntp][0], bF[ntp][1], bF[ntp][2], bF[ntp][3],
                        bBase + (uint32_t)(ks * 16) * BPITCH + ntp * 32);
#pragma unroll
            for (int mt = 0; mt < 4; mt++)
#pragma unroll
                for (int ntp = 0; ntp < 4; ntp++) {
                    mma_f16(acc[mt][2*ntp],   aF[mt], bF[ntp] + 0);
                    mma_f16(acc[mt][2*ntp+1], aF[mt], bF[ntp] + 2);
                }
        }
        __syncthreads();
    }

    // epilogue
    int tr = lane >> 2;
    int tc = (lane & 3) * 2;
#pragma unroll
    for (int mt = 0; mt < 4; mt++) {
#pragma unroll
        for (int half = 0; half < 2; half++) {
            int r = rowBase + wm * 64 + mt * 16 + tr + half * 8;
#pragma unroll
            for (int nt = 0; nt < 8; nt++) {
                int cg = colBase + wn * 64 + nt * 8 + tc;
                size_t off = (size_t)r * N + cg;
                float v0 = acc[mt][nt][half * 2 + 0];
                float v1 = acc[mt][nt][half * 2 + 1];
                if (bias)  { v0 += bias[cg]; v1 += bias[cg + 1]; }
                if (relu)  { v0 = fmaxf(v0, 0.f); v1 = fmaxf(v1, 0.f); }
                if (resid) { v0 += resid[off]; v1 += resid[off + 1]; }
                if (Cf) *(float2*)&Cf[off] = make_float2(v0, v1);
                if (Ch) *(uint32_t*)&Ch[off] = pack_f16(v0, v1);
            }
        }
    }
}

// ---------------- HMMA fp16 flash attention ----------------------------------
// QKV layout [M][3072]: q = h*64+d, k = +1024, v = +2048.
// 256 threads (8 warps), 128 q-rows/block, 64-key chunks, double-buffered K/V.
#define AT_PITCH 144
#define AT_PLANE (64 * AT_PITCH)          // 9216
#define Q_BYTES  (128 * AT_PITCH)         // 18432
#define KV_STAGE (2 * AT_PLANE)           // K + V per stage
#define ATTN_SMEM (Q_BYTES + 2 * KV_STAGE + 256)

__global__ __launch_bounds__(256) void attn_mma(
    const f16* __restrict__ QKV, f16* __restrict__ O)
{
    extern __shared__ char sm_[];
    char* base = (char*)(((uintptr_t)sm_ + 127) & ~(uintptr_t)127);
    uint32_t sb = smem_u32(base);
    uint32_t qS = sb;
    uint32_t kvS = sb + Q_BYTES;          // stage s: K at +s*KV_STAGE, V at +AT_PLANE

    int tid = threadIdx.x, warp = tid >> 5, lane = tid & 31;
    int qt = blockIdx.x, bh = blockIdx.y;
    int b = bh >> 4, h = bh & 15;
    int qrow0 = b * S_ + qt * 128;

    // ---- load Q tile (128 rows x 128B) ----
#pragma unroll
    for (int it = 0; it < 4; it++) {
        int idx = it * 256 + tid;
        int r = idx >> 3, c = idx & 7;
        cp_async16(qS + r * AT_PITCH + c * 16,
                   QKV + (size_t)(qrow0 + r) * (3 * DIM_) + h * HD_ + c * 8);
    }
    cp_commit();

    // ---- K/V chunk loader (64 rows each) ----
    auto load_kv = [&](int kt, int s) {
        uint32_t st = kvS + s * KV_STAGE;
        size_t rowg = (size_t)(b * S_ + kt * 64) * (3 * DIM_) + DIM_ + h * HD_;
#pragma unroll
        for (int it = 0; it < 2; it++) {
            int idx = it * 256 + tid;
            int r = idx >> 3, c = idx & 7;
            size_t g = rowg + (size_t)r * (3 * DIM_) + c * 8;
            cp_async16(st + r * AT_PITCH + c * 16, QKV + g);           // K
            cp_async16(st + AT_PLANE + r * AT_PITCH + c * 16, QKV + g + DIM_); // V
        }
        cp_commit();
    };

    load_kv(0, 0);
    cp_wait<1>();     // Q done (group 0 retired when <=1 pending)
    __syncthreads();

    // ---- preload Q fragments ----
    uint32_t qf[4][4];
    {
        uint32_t aAddr = qS + (uint32_t)(warp * 16 + (lane & 15)) * AT_PITCH
                       + ((lane >> 4) * 16);
#pragma unroll
        for (int ks = 0; ks < 4; ks++)
            ldm_x4(qf[ks][0], qf[ks][1], qf[ks][2], qf[ks][3], aAddr + ks * 32);
    }

    float oacc[8][4];
#pragma unroll
    for (int i = 0; i < 8; i++)
#pragma unroll
        for (int j = 0; j < 4; j++) oacc[i][j] = 0.f;
    float m0 = -1e30f, m1 = -1e30f, l0 = 0.f, l1 = 0.f;

    uint32_t bAddrBase = (uint32_t)(((lane >> 4) & 1) * 8 + (lane & 7)) * AT_PITCH
                       + ((lane >> 3) & 1) * 16;

    const int NT = S_ / 64;
    for (int kt = 0; kt < NT; kt++) {
        int s = kt & 1;
        if (kt + 1 < NT) { load_kv(kt + 1, s ^ 1); cp_wait<1>(); }
        else             { cp_wait<0>(); }
        __syncthreads();

        uint32_t kS = kvS + s * KV_STAGE;
        uint32_t vS = kS + AT_PLANE;

        // ---- S = Q K^T ----
        float sacc[8][4];
#pragma unroll
        for (int i = 0; i < 8; i++)
#pragma unroll
            for (int j = 0; j < 4; j++) sacc[i][j] = 0.f;

#pragma unroll
        for (int ks = 0; ks < 4; ks++) {
#pragma unroll
            for (int ntp = 0; ntp < 4; ntp++) {
                uint32_t addr = kS + bAddrBase + (uint32_t)(ntp * 16) * AT_PITCH + ks * 32;
                uint32_t b4[4];
                ldm_x4(b4[0], b4[1], b4[2], b4[3], addr);
                mma_f16(sacc[2*ntp],   qf[ks], b4 + 0);
                mma_f16(sacc[2*ntp+1], qf[ks], b4 + 2);
            }
        }

        // ---- online softmax ----
        float mx0 = -1e30f, mx1 = -1e30f;
#pragma unroll
        for (int nt = 0; nt < 8; nt++) {
#pragma unroll
            for (int j = 0; j < 4; j++) sacc[nt][j] *= 0.125f;
            mx0 = fmaxf(mx0, fmaxf(sacc[nt][0], sacc[nt][1]));
            mx1 = fmaxf(mx1, fmaxf(sacc[nt][2], sacc[nt][3]));
        }
        mx0 = fmaxf(mx0, __shfl_xor_sync(0xffffffffu, mx0, 1));
        mx0 = fmaxf(mx0, __shfl_xor_sync(0xffffffffu, mx0, 2));
        mx1 = fmaxf(mx1, __shfl_xor_sync(0xffffffffu, mx1, 1));
        mx1 = fmaxf(mx1, __shfl_xor_sync(0xffffffffu, mx1, 2));

        float nm0 = fmaxf(m0, mx0), nm1 = fmaxf(m1, mx1);
        float corr0 = __expf(m0 - nm0), corr1 = __expf(m1 - nm1);
        float rs0 = 0.f, rs1 = 0.f;
#pragma unroll
        for (int nt = 0; nt < 8; nt++) {
            sacc[nt][0] = __expf(sacc[nt][0] - nm0);
            sacc[nt][1] = __expf(sacc[nt][1] - nm0);
            sacc[nt][2] = __expf(sacc[nt][2] - nm1);
            sacc[nt][3] = __expf(sacc[nt][3] - nm1);
            rs0 += sacc[nt][0] + sacc[nt][1];
            rs1 += sacc[nt][2] + sacc[nt][3];
        }
        rs0 += __shfl_xor_sync(0xffffffffu, rs0, 1);
        rs0 += __shfl_xor_sync(0xffffffffu, rs0, 2);
        rs1 += __shfl_xor_sync(0xffffffffu, rs1, 1);
        rs1 += __shfl_xor_sync(0xffffffffu, rs1, 2);
        l0 = l0 * corr0 + rs0;  m0 = nm0;
        l1 = l1 * corr1 + rs1;  m1 = nm1;
#pragma unroll
        for (int nt = 0; nt < 8; nt++) {
            oacc[nt][0] *= corr0; oacc[nt][1] *= corr0;
            oacc[nt][2] *= corr1; oacc[nt][3] *= corr1;
        }

        // ---- O += P V ----
#pragma unroll
        for (int ks = 0; ks < 4; ks++) {
            uint32_t aP[4];
            float* se = sacc[2*ks];
            float* so = sacc[2*ks + 1];
            aP[0] = pack_f16(se[0], se[1]);
            aP[1] = pack_f16(se[2], se[3]);
            aP[2] = pack_f16(so[0], so[1]);
            aP[3] = pack_f16(so[2], so[3]);
#pragma unroll
            for (int ntp = 0; ntp < 4; ntp++) {
                uint32_t addr = vS + (uint32_t)(ks * 16 + (lane & 15)) * AT_PITCH
                              + (uint32_t)(ntp * 2 + ((lane >> 4) & 1)) * 16;
                uint32_t v4[4];
                ldm_x4t(v4[0], v4[1], v4[2], v4[3], addr);
                mma_f16(oacc[2*ntp],   aP, v4 + 0);
                mma_f16(oacc[2*ntp+1], aP, v4 + 2);
            }
        }
        __syncthreads();
    }

    // ---- normalize + write out ----
    float inv0 = 1.f / l0, inv1 = 1.f / l1;
    int r0g = qrow0 + warp * 16 + (lane >> 2);
    int cbase = h * HD_ + (lane & 3) * 2;
#pragma unroll
    for (int nt = 0; nt < 8; nt++) {
        float v0 = oacc[nt][0] * inv0, v1 = oacc[nt][1] * inv0;
        float v2 = oacc[nt][2] * inv1, v3 = oacc[nt][3] * inv1;
        size_t off0 = (size_t)r0g * DIM_ + cbase + nt * 8;
        size_t off1 = off0 + (size_t)8 * DIM_;
        *(uint32_t*)&O[off0] = pack_f16(v0, v1);
        *(uint32_t*)&O[off1] = pack_f16(v2, v3);
    }
}

// ---------------- launcher ---------------------------------------------------
extern "C" void kernel_launch(void* const* d_in, const int* in_sizes, int n_in,
                              void* d_out, int out_size)
{
    const float* x      = (const float*)d_in[0];
    const float* wq     = (const float*)d_in[2];
    const float* wk     = (const float*)d_in[3];
    const float* wv     = (const float*)d_in[4];
    const float* wo     = (const float*)d_in[5];
    const float* w_up   = (const float*)d_in[6];
    const float* b_up   = (const float*)d_in[7];
    const float* w_down = (const float*)d_in[8];
    const float* b_down = (const float*)d_in[9];
    const float* ln1_a  = (const float*)d_in[10];
    const float* ln1_b  = (const float*)d_in[11];
    const float* ln2_a  = (const float*)d_in[12];
    const float* ln2_b  = (const float*)d_in[13];
    float* out = (float*)d_out;

    f16 *lnp, *qkv, *at, *ff, *wqkvC, *woC, *upC, *dnC;
    float *px1;
    cudaGetSymbolAddress((void**)&lnp,   g_ln);
    cudaGetSymbolAddress((void**)&qkv,   g_qkv);
    cudaGetSymbolAddress((void**)&at,    g_at);
    cudaGetSymbolAddress((void**)&ff,    g_ff);
    cudaGetSymbolAddress((void**)&wqkvC, g_wqkv);
    cudaGetSymbolAddress((void**)&woC,   g_wo);
    cudaGetSymbolAddress((void**)&upC,   g_up);
    cudaGetSymbolAddress((void**)&dnC,   g_dn);
    cudaGetSymbolAddress((void**)&px1,   g_x1);

    cudaFuncSetAttribute(gemm_f16, cudaFuncAttributeMaxDynamicSharedMemorySize, GEMM_SMEM);
    cudaFuncSetAttribute(attn_mma, cudaFuncAttributeMaxDynamicSharedMemorySize, ATTN_SMEM);

    // one-shot weight convert (no transpose): 12M elems / 4 per thread
    conv_all<<<12288, 256>>>(wq, wk, wv, wo, w_up, w_down, wqkvC, woC, upC, dnC);

    dim3 blk(256);
    dim3 gD(DIM_/256, M_/128);      // N=1024
    dim3 gQKV(3*DIM_/256, M_/128);  // N=3072
    dim3 gF(DFF_/256, M_/128);      // N=4096

    // h = LN1(x)
    ln_kernel<<<M_, blk>>>(x, ln1_a, ln1_b, lnp);
    // fused QKV projection -> fp16 [M][3072]
    gemm_f16<<<gQKV, blk, GEMM_SMEM>>>(lnp, wqkvC, nullptr, nullptr,
                                       nullptr, qkv, M_, 3*DIM_, DIM_, 0);
    // flash attention -> fp16
    attn_mma<<<dim3(S_/128, B_*NH_), blk, ATTN_SMEM>>>(qkv, at);
    // x1 = x + attn @ wo
    gemm_f16<<<gD, blk, GEMM_SMEM>>>(at, woC, nullptr, x,
                                     px1, nullptr, M_, DIM_, DIM_, 0);
    // h = LN2(x1)
    ln_kernel<<<M_, blk>>>(px1, ln2_a, ln2_b, lnp);
    // ff = relu(h @ w_up + b_up) -> fp16
    gemm_f16<<<gF, blk, GEMM_SMEM>>>(lnp, upC, b_up, nullptr,
                                     nullptr, ff, M_, DFF_, DIM_, 1);
    // out = x1 + ff @ w_down + b_down
    gemm_f16<<<gD, blk, GEMM_SMEM>>>(ff, dnC, b_down, px1,
                                     out, nullptr, M_, DIM_, DFF_, 0);
}